// round 1
// baseline (speedup 1.0000x reference)
#include <cuda_runtime.h>
#include <cstddef>

#define B_   8
#define P_   196
#define L_   80
#define D1   2048
#define D2   300
#define ATT  1024
// 2*log2(e): p2 is pre-scaled by this so exp2(p1*p2s) == exp(2*p1*p2)
#define TWO_LOG2E 2.8853900817779268f

// Scratch (no allocations allowed)
__device__ float g_p1[B_ * P_ * ATT];   // 6.4 MB
__device__ float g_p2[B_ * L_ * ATT];   // 2.6 MB  (pre-scaled by TWO_LOG2E)
__device__ float g_v[ATT];
__device__ float g_cst;

// ---------------------------------------------------------------------------
// SGEMM NT: C[m][n] = scale * sum_k A[m][k] * B[n][k]
// Block tile 128(M) x 64(N), 256 threads, 8x4 micro-tile, K-chunk 16.
// ---------------------------------------------------------------------------
__global__ void __launch_bounds__(256) sgemm_nt_kernel(
    const float* __restrict__ A, const float* __restrict__ Bm,
    float* __restrict__ C, int M, int N, int K, float scale)
{
    __shared__ float As[16][132];  // As[k][m], padded
    __shared__ float Bs[16][68];   // Bs[k][n], padded

    const int m0 = blockIdx.y * 128;
    const int n0 = blockIdx.x * 64;
    const int t  = threadIdx.x;
    const int tx = t & 15;   // n micro index (4 cols each)
    const int ty = t >> 4;   // m micro index (8 rows each)

    float acc[8][4];
#pragma unroll
    for (int i = 0; i < 8; i++)
#pragma unroll
        for (int j = 0; j < 4; j++) acc[i][j] = 0.0f;

    for (int k0 = 0; k0 < K; k0 += 16) {
        __syncthreads();
        const bool ktail = (k0 + 16 > K);
        if (!ktail) {
            // A tile: 128x16 = 512 float4, 2 per thread
#pragma unroll
            for (int it = 0; it < 2; it++) {
                int f = t + it * 256;
                int m = f >> 2;
                int kq = (f & 3) << 2;
                float4 val = make_float4(0.f, 0.f, 0.f, 0.f);
                if (m0 + m < M)
                    val = *reinterpret_cast<const float4*>(
                        &A[(size_t)(m0 + m) * K + k0 + kq]);
                As[kq + 0][m] = val.x;
                As[kq + 1][m] = val.y;
                As[kq + 2][m] = val.z;
                As[kq + 3][m] = val.w;
            }
            // B tile: 64x16 = 256 float4, 1 per thread
            {
                int n = t >> 2;
                int kq = (t & 3) << 2;
                float4 val = *reinterpret_cast<const float4*>(
                    &Bm[(size_t)(n0 + n) * K + k0 + kq]);
                Bs[kq + 0][n] = val.x;
                Bs[kq + 1][n] = val.y;
                Bs[kq + 2][n] = val.z;
                Bs[kq + 3][n] = val.w;
            }
        } else {
            // guarded scalar tail (only for K=300 last chunk)
            for (int i = t; i < 128 * 16; i += 256) {
                int m = i >> 4, k = i & 15;
                float v = 0.0f;
                if (m0 + m < M && k0 + k < K)
                    v = A[(size_t)(m0 + m) * K + k0 + k];
                As[k][m] = v;
            }
            for (int i = t; i < 64 * 16; i += 256) {
                int n = i >> 4, k = i & 15;
                float v = 0.0f;
                if (k0 + k < K)
                    v = Bm[(size_t)(n0 + n) * K + k0 + k];
                Bs[k][n] = v;
            }
        }
        __syncthreads();

#pragma unroll
        for (int k = 0; k < 16; k++) {
            float a8[8], b4[4];
#pragma unroll
            for (int i = 0; i < 8; i++) a8[i] = As[k][ty * 8 + i];
#pragma unroll
            for (int j = 0; j < 4; j++) b4[j] = Bs[k][tx * 4 + j];
#pragma unroll
            for (int i = 0; i < 8; i++)
#pragma unroll
                for (int j = 0; j < 4; j++)
                    acc[i][j] = fmaf(a8[i], b4[j], acc[i][j]);
        }
    }

#pragma unroll
    for (int i = 0; i < 8; i++) {
        int row = m0 + ty * 8 + i;
        if (row < M) {
            float4 o;
            o.x = acc[i][0] * scale;
            o.y = acc[i][1] * scale;
            o.z = acc[i][2] * scale;
            o.w = acc[i][3] * scale;
            *reinterpret_cast<float4*>(&C[(size_t)row * N + n0 + tx * 4]) = o;
        }
    }
}

// ---------------------------------------------------------------------------
// v[a] = sum_c wt[c] * Wh[c][a]     (grid 8 x 128 threads)
// ---------------------------------------------------------------------------
__global__ void __launch_bounds__(128) compute_v_kernel(
    const float* __restrict__ Wh, const float* __restrict__ wt)
{
    int a = blockIdx.x * 128 + threadIdx.x;
    float acc = 0.0f;
#pragma unroll 4
    for (int c = 0; c < ATT; c++)
        acc = fmaf(wt[c], Wh[(size_t)c * ATT + a], acc);
    g_v[a] = acc;
}

// ---------------------------------------------------------------------------
// cst = dot(wt, bh) + bt           (1 block)
// ---------------------------------------------------------------------------
__global__ void __launch_bounds__(256) compute_cst_kernel(
    const float* __restrict__ wt, const float* __restrict__ bh,
    const float* __restrict__ bt)
{
    __shared__ float red[256];
    float acc = 0.0f;
    for (int i = threadIdx.x; i < ATT; i += 256)
        acc = fmaf(wt[i], bh[i], acc);
    red[threadIdx.x] = acc;
    __syncthreads();
    for (int s = 128; s > 0; s >>= 1) {
        if (threadIdx.x < s) red[threadIdx.x] += red[threadIdx.x + s];
        __syncthreads();
    }
    if (threadIdx.x == 0) g_cst = red[0] + bt[0];
}

// ---------------------------------------------------------------------------
// Main: alpha[b,l,p] = sum_a tanh(p1[b,p,a]*p2[b,l,a]) * v[a] + cst
// tanh(x) = 1 - 2/(exp2(arg)+1), arg = p1 * p2s  (p2s pre-scaled by 2*log2 e)
// Block: 256 threads = 16(p) x 16(l) outputs, a-chunks of 128 via shared.
// ---------------------------------------------------------------------------
__global__ void __launch_bounds__(256) bilinear_tanh_kernel(
    float* __restrict__ out)
{
    __shared__ float p1s[128][17];  // [a][p] transposed, padded
    __shared__ float p2s[128][17];  // [a][l] transposed, padded
    __shared__ float vs[128];

    const int b  = blockIdx.z;
    const int l0 = blockIdx.y * 16;
    const int p0 = blockIdx.x * 16;
    const int t  = threadIdx.x;
    const int tx = t & 15;   // p
    const int ty = t >> 4;   // l

    const float* __restrict__ p1b = g_p1 + ((size_t)b * P_ + p0) * ATT;
    const float* __restrict__ p2b = g_p2 + ((size_t)b * L_ + l0) * ATT;

    float acc = 0.0f;

    for (int a0 = 0; a0 < ATT; a0 += 128) {
        __syncthreads();
        // load 16 rows x 128 a for both p1 and p2 (transposed into shared)
        for (int i = t; i < 16 * 128; i += 256) {
            int r = i >> 7;
            int a = i & 127;
            float v1 = 0.0f;
            if (p0 + r < P_) v1 = p1b[(size_t)r * ATT + a0 + a];
            p1s[a][r] = v1;
            p2s[a][r] = p2b[(size_t)r * ATT + a0 + a];  // l0+r < 80 always
        }
        if (t < 128) vs[t] = g_v[a0 + t];
        __syncthreads();

#pragma unroll 8
        for (int j = 0; j < 128; j++) {
            float arg = p1s[j][tx] * p2s[j][ty];
            float e;
            asm("ex2.approx.f32 %0, %1;" : "=f"(e) : "f"(arg));
            float r;
            asm("rcp.approx.f32 %0, %1;" : "=f"(r) : "f"(e + 1.0f));
            // tanh = 1 - 2r  (exact limits at +/-inf, no NaN)
            acc = fmaf(fmaf(-2.0f, r, 1.0f), vs[j], acc);
        }
    }

    int p = p0 + tx;
    int l = l0 + ty;
    if (p < P_)
        out[((size_t)b * L_ + l) * P_ + p] = acc + g_cst;
}

// ---------------------------------------------------------------------------
extern "C" void kernel_launch(void* const* d_in, const int* in_sizes, int n_in,
                              void* d_out, int out_size)
{
    const float* x1 = (const float*)d_in[0];
    const float* x2 = (const float*)d_in[1];
    const float* W1 = (const float*)d_in[2];
    const float* W2 = (const float*)d_in[3];
    const float* Wh = (const float*)d_in[4];
    const float* bh = (const float*)d_in[5];
    const float* wt = (const float*)d_in[6];
    const float* bt = (const float*)d_in[7];
    float* out = (float*)d_out;

    void* p1_ptr = nullptr;
    void* p2_ptr = nullptr;
    cudaGetSymbolAddress(&p1_ptr, g_p1);
    cudaGetSymbolAddress(&p2_ptr, g_p2);

    // p1 = x1 @ W1^T : M=1568, N=1024, K=2048
    {
        dim3 grid(ATT / 64, (B_ * P_ + 127) / 128);
        sgemm_nt_kernel<<<grid, 256>>>(x1, W1, (float*)p1_ptr,
                                       B_ * P_, ATT, D1, 1.0f);
    }
    // p2 = (x2 @ W2^T) * 2log2e : M=640, N=1024, K=300
    {
        dim3 grid(ATT / 64, (B_ * L_ + 127) / 128);
        sgemm_nt_kernel<<<grid, 256>>>(x2, W2, (float*)p2_ptr,
                                       B_ * L_, ATT, D2, TWO_LOG2E);
    }
    // v = wt @ Wh ; cst = wt.bh + bt
    compute_v_kernel<<<ATT / 128, 128>>>(Wh, wt);
    compute_cst_kernel<<<1, 256>>>(wt, bh, bt);

    // main fused tanh-bilinear reduction
    {
        dim3 grid((P_ + 15) / 16, L_ / 16, B_);
        bilinear_tanh_kernel<<<grid, 256>>>(out);
    }
}

// round 4
// speedup vs baseline: 1.1179x; 1.1179x over previous
#include <cuda_runtime.h>
#include <cuda_bf16.h>
#include <cstddef>
#include <cstdint>

#define B_   8
#define P_   196
#define L_   80
#define D1   2048
#define D2   300
#define ATT  1024
// 2*log2(e): p2 is pre-scaled so exp2(p1*p2s) == exp(2*p1*p2)
#define TWO_LOG2E 2.8853900817779268f

#define M1   (B_ * P_)      // 1568
#define M2   (B_ * L_)      // 640
#define K1CAT (3 * D1)      // 6144  (multiple of 32)
#define K2CAT 928           // 3*300=900 padded to 928 (multiple of 32)

// ---------------- scratch (no allocations allowed) ----------------
__device__ float g_p1[M1 * ATT];                 // 6.4 MB
__device__ float g_p2[M2 * ATT];                 // 2.6 MB (pre-scaled by TWO_LOG2E)
__device__ float g_v[ATT];
__device__ float g_cst;
__device__ __nv_bfloat16 g_a1[(size_t)M1 * K1CAT];   // 19.3 MB  [Ah|Al|Ah]
__device__ __nv_bfloat16 g_b1[(size_t)ATT * K1CAT];  // 12.6 MB  [Bh|Bh|Bl]
__device__ __nv_bfloat16 g_a2[(size_t)M2 * K2CAT];   // 1.2 MB
__device__ __nv_bfloat16 g_b2[(size_t)ATT * K2CAT];  // 1.9 MB

// ---------------------------------------------------------------------------
// Split fp32 -> (hi, lo) bf16 and write K-concatenated buffer.
// bmode 0 (A): [hi | lo | hi] ;  bmode 1 (B): [hi | hi | lo]
// Each thread handles 4 consecutive k.
// ---------------------------------------------------------------------------
__global__ void __launch_bounds__(256) split_cat_kernel(
    const float* __restrict__ src, __nv_bfloat16* __restrict__ dst,
    int total4, int Kq, int K, int Kcat, int bmode)
{
    int i = blockIdx.x * 256 + threadIdx.x;
    if (i >= total4) return;
    int r = i / Kq;
    int k = (i - r * Kq) * 4;

    float4 x = *reinterpret_cast<const float4*>(src + (size_t)r * K + k);
    float xs[4] = {x.x, x.y, x.z, x.w};
    unsigned short hs[4], ls[4];
#pragma unroll
    for (int j = 0; j < 4; j++) {
        __nv_bfloat16 h = __float2bfloat16(xs[j]);
        __nv_bfloat16 l = __float2bfloat16(xs[j] - __bfloat162float(h));
        hs[j] = __bfloat16_as_ushort(h);
        ls[j] = __bfloat16_as_ushort(l);
    }
    uint2 H, L;
    H.x = (unsigned)hs[0] | ((unsigned)hs[1] << 16);
    H.y = (unsigned)hs[2] | ((unsigned)hs[3] << 16);
    L.x = (unsigned)ls[0] | ((unsigned)ls[1] << 16);
    L.y = (unsigned)ls[2] | ((unsigned)ls[3] << 16);

    size_t base = (size_t)r * Kcat + k;
    if (bmode == 0) {
        *reinterpret_cast<uint2*>(dst + base)         = H;
        *reinterpret_cast<uint2*>(dst + base + K)     = L;
        *reinterpret_cast<uint2*>(dst + base + 2 * K) = H;
    } else {
        *reinterpret_cast<uint2*>(dst + base)         = H;
        *reinterpret_cast<uint2*>(dst + base + K)     = H;
        *reinterpret_cast<uint2*>(dst + base + 2 * K) = L;
    }
}

// ---------------------------------------------------------------------------
// bf16 tensor-core GEMM NT: C[m][n] = scale * sum_k A[m][k] * B[n][k]
// Block 128x128, 256 threads (8 warps, 2x4), warp tile 64x32.
// K-chunk 32, cp.async double buffered, 80B-padded smem rows (conflict-free
// ldmatrix). mma.sync.m16n8k16 bf16 -> f32.
// ---------------------------------------------------------------------------
#define SROW 40          // bf16 elements per smem row (80 bytes)
#define STAGE_B (128 * SROW * 2)  // bytes per stage

__global__ void __launch_bounds__(256) mma_gemm_nt(
    const __nv_bfloat16* __restrict__ A, const __nv_bfloat16* __restrict__ Bm,
    float* __restrict__ C, int M, int N, int Kcat, float scale)
{
    __shared__ __align__(16) __nv_bfloat16 As[2][128 * SROW];
    __shared__ __align__(16) __nv_bfloat16 Bs[2][128 * SROW];

    const int t    = threadIdx.x;
    const int lane = t & 31;
    const int warp = t >> 5;
    const int wm   = (warp >> 2) * 64;   // 0 or 64
    const int wn   = (warp & 3) * 32;    // 0,32,64,96
    const int m0   = blockIdx.y * 128;
    const int n0   = blockIdx.x * 128;

    const uint32_t sA = (uint32_t)__cvta_generic_to_shared(&As[0][0]);
    const uint32_t sB = (uint32_t)__cvta_generic_to_shared(&Bs[0][0]);

    float c[4][4][4];
#pragma unroll
    for (int i = 0; i < 4; i++)
#pragma unroll
        for (int j = 0; j < 4; j++)
#pragma unroll
            for (int r = 0; r < 4; r++) c[i][j][r] = 0.0f;

    const int nk = Kcat / 32;

    // loader: each thread moves 2x16B for A and 2x16B for B per chunk
    const int lrow0 = t >> 2;        // 0..63
    const int lseg  = (t & 3) * 8;   // element offset of 16B segment

#define LOAD_CHUNK(kc, st) do {                                               \
    _Pragma("unroll")                                                         \
    for (int it = 0; it < 2; it++) {                                          \
        int row = lrow0 + it * 64;                                            \
        int ga  = m0 + row;                                                   \
        const __nv_bfloat16* srcA = A + (size_t)ga * Kcat + (kc) * 32 + lseg; \
        uint32_t dstA = sA + (st) * STAGE_B + row * (SROW * 2) + lseg * 2;    \
        int bytesA = (ga < M) ? 16 : 0;                                       \
        asm volatile("cp.async.cg.shared.global [%0], [%1], 16, %2;\n"        \
                     :: "r"(dstA), "l"(srcA), "r"(bytesA));                   \
        const __nv_bfloat16* srcB = Bm + (size_t)(n0 + row) * Kcat + (kc) * 32 + lseg; \
        uint32_t dstB = sB + (st) * STAGE_B + row * (SROW * 2) + lseg * 2;    \
        asm volatile("cp.async.cg.shared.global [%0], [%1], 16;\n"            \
                     :: "r"(dstB), "l"(srcB));                                \
    }                                                                          \
} while (0)

#define COMPUTE_CHUNK(st) do {                                                \
    _Pragma("unroll")                                                         \
    for (int ks = 0; ks < 2; ks++) {                                          \
        int koff = ks * 16;                                                   \
        uint32_t a[4][4];                                                     \
        _Pragma("unroll")                                                     \
        for (int i = 0; i < 4; i++) {                                         \
            uint32_t addr = sA + (st) * STAGE_B                               \
                + (wm + i * 16 + (lane & 15)) * (SROW * 2)                    \
                + ((lane >> 4) * 8 + koff) * 2;                               \
            asm volatile("ldmatrix.sync.aligned.m8n8.x4.shared.b16 "          \
                         "{%0,%1,%2,%3}, [%4];\n"                             \
                         : "=r"(a[i][0]), "=r"(a[i][1]),                      \
                           "=r"(a[i][2]), "=r"(a[i][3]) : "r"(addr));         \
        }                                                                     \
        uint32_t b[4][2];                                                     \
        _Pragma("unroll")                                                     \
        for (int j2 = 0; j2 < 2; j2++) {                                      \
            uint32_t addr = sB + (st) * STAGE_B                               \
                + (wn + j2 * 16 + (lane & 15)) * (SROW * 2)                   \
                + ((lane >> 4) * 8 + koff) * 2;                               \
            uint32_t r0, r1, r2, r3;                                          \
            asm volatile("ldmatrix.sync.aligned.m8n8.x4.shared.b16 "          \
                         "{%0,%1,%2,%3}, [%4];\n"                             \
                         : "=r"(r0), "=r"(r1), "=r"(r2), "=r"(r3)             \
                         : "r"(addr));                                        \
            b[2 * j2][0] = r0; b[2 * j2 + 1][0] = r1;                         \
            b[2 * j2][1] = r2; b[2 * j2 + 1][1] = r3;                         \
        }                                                                     \
        _Pragma("unroll")                                                     \
        for (int i = 0; i < 4; i++)                                           \
            _Pragma("unroll")                                                 \
            for (int j = 0; j < 4; j++)                                       \
                asm volatile(                                                 \
                  "mma.sync.aligned.m16n8k16.row.col.f32.bf16.bf16.f32 "      \
                  "{%0,%1,%2,%3}, {%4,%5,%6,%7}, {%8,%9}, {%0,%1,%2,%3};\n"   \
                  : "+f"(c[i][j][0]), "+f"(c[i][j][1]),                       \
                    "+f"(c[i][j][2]), "+f"(c[i][j][3])                        \
                  : "r"(a[i][0]), "r"(a[i][1]), "r"(a[i][2]), "r"(a[i][3]),   \
                    "r"(b[j][0]), "r"(b[j][1]));                              \
    }                                                                          \
} while (0)

    LOAD_CHUNK(0, 0);
    asm volatile("cp.async.commit_group;\n");

    for (int kc = 0; kc < nk; kc++) {
        int st = kc & 1;
        if (kc + 1 < nk) {
            LOAD_CHUNK(kc + 1, (kc + 1) & 1);
            asm volatile("cp.async.commit_group;\n");
            asm volatile("cp.async.wait_group 1;\n");
        } else {
            asm volatile("cp.async.wait_group 0;\n");
        }
        __syncthreads();
        COMPUTE_CHUNK(st);
        __syncthreads();
    }

    // epilogue
#pragma unroll
    for (int i = 0; i < 4; i++) {
        int row0 = m0 + wm + i * 16 + (lane >> 2);
#pragma unroll
        for (int j = 0; j < 4; j++) {
            int col = n0 + wn + j * 8 + (lane & 3) * 2;
            if (row0 < M) {
                float2 o = make_float2(c[i][j][0] * scale, c[i][j][1] * scale);
                *reinterpret_cast<float2*>(&C[(size_t)row0 * N + col]) = o;
            }
            if (row0 + 8 < M) {
                float2 o = make_float2(c[i][j][2] * scale, c[i][j][3] * scale);
                *reinterpret_cast<float2*>(&C[(size_t)(row0 + 8) * N + col]) = o;
            }
        }
    }
}

// ---------------------------------------------------------------------------
// v[a] = sum_c wt[c] * Wh[c][a]
// ---------------------------------------------------------------------------
__global__ void __launch_bounds__(128) compute_v_kernel(
    const float* __restrict__ Wh, const float* __restrict__ wt)
{
    int a = blockIdx.x * 128 + threadIdx.x;
    float acc = 0.0f;
#pragma unroll 4
    for (int c = 0; c < ATT; c++)
        acc = fmaf(wt[c], Wh[(size_t)c * ATT + a], acc);
    g_v[a] = acc;
}

// ---------------------------------------------------------------------------
// cst = dot(wt, bh) + bt
// ---------------------------------------------------------------------------
__global__ void __launch_bounds__(256) compute_cst_kernel(
    const float* __restrict__ wt, const float* __restrict__ bh,
    const float* __restrict__ bt)
{
    __shared__ float red[256];
    float acc = 0.0f;
    for (int i = threadIdx.x; i < ATT; i += 256)
        acc = fmaf(wt[i], bh[i], acc);
    red[threadIdx.x] = acc;
    __syncthreads();
    for (int s = 128; s > 0; s >>= 1) {
        if (threadIdx.x < s) red[threadIdx.x] += red[threadIdx.x + s];
        __syncthreads();
    }
    if (threadIdx.x == 0) g_cst = red[0] + bt[0];
}

// ---------------------------------------------------------------------------
// Main: alpha[b,l,p] = sum_a tanh(p1*p2) * v[a] + cst
// tanh(x) = 1 - 2/(exp2(p1*p2s)+1)   (p2s pre-scaled by 2*log2 e)
// ---------------------------------------------------------------------------
__global__ void __launch_bounds__(256) bilinear_tanh_kernel(
    float* __restrict__ out)
{
    __shared__ float p1s[128][17];
    __shared__ float p2s[128][17];
    __shared__ float vs[128];

    const int b  = blockIdx.z;
    const int l0 = blockIdx.y * 16;
    const int p0 = blockIdx.x * 16;
    const int t  = threadIdx.x;
    const int tx = t & 15;   // p
    const int ty = t >> 4;   // l

    const float* __restrict__ p1b = g_p1 + ((size_t)b * P_ + p0) * ATT;
    const float* __restrict__ p2b = g_p2 + ((size_t)b * L_ + l0) * ATT;

    float acc = 0.0f;

    for (int a0 = 0; a0 < ATT; a0 += 128) {
        __syncthreads();
        for (int i = t; i < 16 * 128; i += 256) {
            int r = i >> 7;
            int a = i & 127;
            float v1 = 0.0f;
            if (p0 + r < P_) v1 = p1b[(size_t)r * ATT + a0 + a];
            p1s[a][r] = v1;
            p2s[a][r] = p2b[(size_t)r * ATT + a0 + a];
        }
        if (t < 128) vs[t] = g_v[a0 + t];
        __syncthreads();

#pragma unroll 8
        for (int j = 0; j < 128; j++) {
            float arg = p1s[j][tx] * p2s[j][ty];
            float e;
            asm("ex2.approx.f32 %0, %1;" : "=f"(e) : "f"(arg));
            float r;
            asm("rcp.approx.f32 %0, %1;" : "=f"(r) : "f"(e + 1.0f));
            acc = fmaf(fmaf(-2.0f, r, 1.0f), vs[j], acc);
        }
    }

    int p = p0 + tx;
    int l = l0 + ty;
    if (p < P_)
        out[((size_t)b * L_ + l) * P_ + p] = acc + g_cst;
}

// ---------------------------------------------------------------------------
extern "C" void kernel_launch(void* const* d_in, const int* in_sizes, int n_in,
                              void* d_out, int out_size)
{
    const float* x1 = (const float*)d_in[0];
    const float* x2 = (const float*)d_in[1];
    const float* W1 = (const float*)d_in[2];
    const float* W2 = (const float*)d_in[3];
    const float* Wh = (const float*)d_in[4];
    const float* bh = (const float*)d_in[5];
    const float* wt = (const float*)d_in[6];
    const float* bt = (const float*)d_in[7];
    float* out = (float*)d_out;

    void *p1_ptr, *p2_ptr, *a1_ptr, *b1_ptr, *a2_ptr, *b2_ptr;
    cudaGetSymbolAddress(&p1_ptr, g_p1);
    cudaGetSymbolAddress(&p2_ptr, g_p2);
    cudaGetSymbolAddress(&a1_ptr, g_a1);
    cudaGetSymbolAddress(&b1_ptr, g_b1);
    cudaGetSymbolAddress(&a2_ptr, g_a2);
    cudaGetSymbolAddress(&b2_ptr, g_b2);

    // zero K-pad of the gemm2 operand buffers (900..928 per row)
    cudaMemsetAsync(a2_ptr, 0, (size_t)M2 * K2CAT * sizeof(__nv_bfloat16));
    cudaMemsetAsync(b2_ptr, 0, (size_t)ATT * K2CAT * sizeof(__nv_bfloat16));

    // split + concat prep
    {
        int t4 = M1 * (D1 / 4);
        split_cat_kernel<<<(t4 + 255) / 256, 256>>>(x1, (__nv_bfloat16*)a1_ptr,
                                                    t4, D1 / 4, D1, K1CAT, 0);
    }
    {
        int t4 = ATT * (D1 / 4);
        split_cat_kernel<<<(t4 + 255) / 256, 256>>>(W1, (__nv_bfloat16*)b1_ptr,
                                                    t4, D1 / 4, D1, K1CAT, 1);
    }
    {
        int t4 = M2 * (D2 / 4);
        split_cat_kernel<<<(t4 + 255) / 256, 256>>>(x2, (__nv_bfloat16*)a2_ptr,
                                                    t4, D2 / 4, D2, K2CAT, 0);
    }
    {
        int t4 = ATT * (D2 / 4);
        split_cat_kernel<<<(t4 + 255) / 256, 256>>>(W2, (__nv_bfloat16*)b2_ptr,
                                                    t4, D2 / 4, D2, K2CAT, 1);
    }

    // p1 = x1 @ W1^T  (tensor cores, split-bf16): M=1568, N=1024, Kcat=6144
    {
        dim3 grid(ATT / 128, (M1 + 127) / 128);
        mma_gemm_nt<<<grid, 256>>>((const __nv_bfloat16*)a1_ptr,
                                   (const __nv_bfloat16*)b1_ptr,
                                   (float*)p1_ptr, M1, ATT, K1CAT, 1.0f);
    }
    // p2 = (x2 @ W2^T) * 2log2e : M=640, N=1024, Kcat=928
    {
        dim3 grid(ATT / 128, (M2 + 127) / 128);
        mma_gemm_nt<<<grid, 256>>>((const __nv_bfloat16*)a2_ptr,
                                   (const __nv_bfloat16*)b2_ptr,
                                   (float*)p2_ptr, M2, ATT, K2CAT, TWO_LOG2E);
    }

    compute_v_kernel<<<ATT / 128, 128>>>(Wh, wt);
    compute_cst_kernel<<<1, 256>>>(wt, bh, bt);

    {
        dim3 grid((P_ + 15) / 16, L_ / 16, B_);
        bilinear_tanh_kernel<<<grid, 256>>>(out);
    }
}

// round 6
// speedup vs baseline: 1.3782x; 1.2328x over previous
#include <cuda_runtime.h>
#include <cuda_bf16.h>
#include <cstddef>
#include <cstdint>

#define B_   8
#define P_   196
#define L_   80
#define D1   2048
#define D2   300
#define ATT  1024
#define TWO_LOG2E 2.8853900817779268f

#define M1   (B_ * P_)      // 1568
#define M2   (B_ * L_)      // 640
#define K1CAT (3 * D1)      // 6144
#define K2CAT 928           // 3*300=900 padded to 928

#define KSPLIT 4
#define NK1    (K1CAT / 32)         // 192 chunks
#define CPS1   (NK1 / KSPLIT)       // 48
#define NK2    (K2CAT / 32)         // 29 chunks
#define CPS2   8                    // 8,8,8,5

// ---------------- scratch (no allocations allowed) ----------------
__device__ float g_p1[M1 * ATT];
__device__ float g_p2[M2 * ATT];
__device__ float g_p1part[(size_t)KSPLIT * M1 * ATT];   // 25.7 MB
__device__ float g_p2part[(size_t)KSPLIT * M2 * ATT];   // 10.5 MB
__device__ float g_v[ATT];
__device__ float g_cst;
__device__ __nv_bfloat16 g_a1[(size_t)M1 * K1CAT];
__device__ __nv_bfloat16 g_b1[(size_t)ATT * K1CAT];
__device__ __nv_bfloat16 g_a2[(size_t)M2 * K2CAT];
__device__ __nv_bfloat16 g_b2[(size_t)ATT * K2CAT];

// ---------------------------------------------------------------------------
// Split fp32 -> (hi, lo) bf16, K-concatenated: A:[hi|lo|hi]  B:[hi|hi|lo]
// ---------------------------------------------------------------------------
__global__ void __launch_bounds__(256) split_cat_kernel(
    const float* __restrict__ src, __nv_bfloat16* __restrict__ dst,
    int total4, int Kq, int K, int Kcat, int bmode)
{
    int i = blockIdx.x * 256 + threadIdx.x;
    if (i >= total4) return;
    int r = i / Kq;
    int k = (i - r * Kq) * 4;

    float4 x = *reinterpret_cast<const float4*>(src + (size_t)r * K + k);
    float xs[4] = {x.x, x.y, x.z, x.w};
    unsigned short hs[4], ls[4];
#pragma unroll
    for (int j = 0; j < 4; j++) {
        __nv_bfloat16 h = __float2bfloat16(xs[j]);
        __nv_bfloat16 l = __float2bfloat16(xs[j] - __bfloat162float(h));
        hs[j] = __bfloat16_as_ushort(h);
        ls[j] = __bfloat16_as_ushort(l);
    }
    uint2 H, L;
    H.x = (unsigned)hs[0] | ((unsigned)hs[1] << 16);
    H.y = (unsigned)hs[2] | ((unsigned)hs[3] << 16);
    L.x = (unsigned)ls[0] | ((unsigned)ls[1] << 16);
    L.y = (unsigned)ls[2] | ((unsigned)ls[3] << 16);

    size_t base = (size_t)r * Kcat + k;
    if (bmode == 0) {
        *reinterpret_cast<uint2*>(dst + base)         = H;
        *reinterpret_cast<uint2*>(dst + base + K)     = L;
        *reinterpret_cast<uint2*>(dst + base + 2 * K) = H;
    } else {
        *reinterpret_cast<uint2*>(dst + base)         = H;
        *reinterpret_cast<uint2*>(dst + base + K)     = H;
        *reinterpret_cast<uint2*>(dst + base + 2 * K) = L;
    }
}

// ---------------------------------------------------------------------------
// bf16 MMA GEMM NT, multi-stage pipeline, split-K partial outputs.
// Block 128x128, 256 thr (8 warps 2x4), warp 64x32, K-chunk 32, STAGES=4.
// ---------------------------------------------------------------------------
#define STAGES 4
#define SROW 40                       // bf16 per smem row (80B)
#define STG_B (128 * SROW * 2)        // 10240 B per operand-stage
#define DSMEM (2 * STAGES * STG_B)    // 81920 B

__global__ void __launch_bounds__(256) mma_gemm_nt_ms(
    const __nv_bfloat16* __restrict__ A, const __nv_bfloat16* __restrict__ Bm,
    float* __restrict__ Cpart, int M, int N, int Kld,
    int total_chunks, int chunks_per_split)
{
    extern __shared__ __align__(16) char smem_raw[];
    const uint32_t sA0 = (uint32_t)__cvta_generic_to_shared(smem_raw);
    const uint32_t sB0 = sA0 + STAGES * STG_B;

    const int t    = threadIdx.x;
    const int lane = t & 31;
    const int warp = t >> 5;
    const int wm   = (warp >> 2) * 64;
    const int wn   = (warp & 3) * 32;
    const int m0   = blockIdx.y * 128;
    const int n0   = blockIdx.x * 128;
    const int ks   = blockIdx.z;
    const int kbeg = ks * chunks_per_split;
    int nk = total_chunks - kbeg;
    if (nk > chunks_per_split) nk = chunks_per_split;
    float* __restrict__ C = Cpart + (size_t)ks * M * N;

    float c[4][4][4];
#pragma unroll
    for (int i = 0; i < 4; i++)
#pragma unroll
        for (int j = 0; j < 4; j++)
#pragma unroll
            for (int r = 0; r < 4; r++) c[i][j][r] = 0.0f;

    const int lrow0 = t >> 2;
    const int lseg  = (t & 3) * 8;

#define LOADC(kc, st) do {                                                    \
    _Pragma("unroll")                                                         \
    for (int it = 0; it < 2; it++) {                                          \
        int row = lrow0 + it * 64;                                            \
        int ga  = m0 + row;                                                   \
        const __nv_bfloat16* srcA = A + (size_t)ga * Kld + (kc) * 32 + lseg;  \
        uint32_t dstA = sA0 + (st) * STG_B + row * (SROW * 2) + lseg * 2;     \
        int bytesA = (ga < M) ? 16 : 0;                                       \
        asm volatile("cp.async.cg.shared.global [%0], [%1], 16, %2;\n"        \
                     :: "r"(dstA), "l"(srcA), "r"(bytesA));                   \
        const __nv_bfloat16* srcB = Bm + (size_t)(n0 + row) * Kld + (kc) * 32 + lseg; \
        uint32_t dstB = sB0 + (st) * STG_B + row * (SROW * 2) + lseg * 2;     \
        asm volatile("cp.async.cg.shared.global [%0], [%1], 16;\n"            \
                     :: "r"(dstB), "l"(srcB));                                \
    }                                                                          \
} while (0)

#define COMPUTEC(st) do {                                                     \
    _Pragma("unroll")                                                         \
    for (int ksub = 0; ksub < 2; ksub++) {                                    \
        int koff = ksub * 16;                                                 \
        uint32_t a[4][4];                                                     \
        _Pragma("unroll")                                                     \
        for (int i = 0; i < 4; i++) {                                         \
            uint32_t addr = sA0 + (st) * STG_B                                \
                + (wm + i * 16 + (lane & 15)) * (SROW * 2)                    \
                + ((lane >> 4) * 8 + koff) * 2;                               \
            asm volatile("ldmatrix.sync.aligned.m8n8.x4.shared.b16 "          \
                         "{%0,%1,%2,%3}, [%4];\n"                             \
                         : "=r"(a[i][0]), "=r"(a[i][1]),                      \
                           "=r"(a[i][2]), "=r"(a[i][3]) : "r"(addr));         \
        }                                                                     \
        uint32_t b[4][2];                                                     \
        _Pragma("unroll")                                                     \
        for (int j2 = 0; j2 < 2; j2++) {                                      \
            uint32_t addr = sB0 + (st) * STG_B                                \
                + (wn + j2 * 16 + (lane & 15)) * (SROW * 2)                   \
                + ((lane >> 4) * 8 + koff) * 2;                               \
            uint32_t r0, r1, r2, r3;                                          \
            asm volatile("ldmatrix.sync.aligned.m8n8.x4.shared.b16 "          \
                         "{%0,%1,%2,%3}, [%4];\n"                             \
                         : "=r"(r0), "=r"(r1), "=r"(r2), "=r"(r3)             \
                         : "r"(addr));                                        \
            b[2 * j2][0] = r0; b[2 * j2 + 1][0] = r1;                         \
            b[2 * j2][1] = r2; b[2 * j2 + 1][1] = r3;                         \
        }                                                                     \
        _Pragma("unroll")                                                     \
        for (int i = 0; i < 4; i++)                                           \
            _Pragma("unroll")                                                 \
            for (int j = 0; j < 4; j++)                                       \
                asm volatile(                                                 \
                  "mma.sync.aligned.m16n8k16.row.col.f32.bf16.bf16.f32 "      \
                  "{%0,%1,%2,%3}, {%4,%5,%6,%7}, {%8,%9}, {%0,%1,%2,%3};\n"   \
                  : "+f"(c[i][j][0]), "+f"(c[i][j][1]),                       \
                    "+f"(c[i][j][2]), "+f"(c[i][j][3])                        \
                  : "r"(a[i][0]), "r"(a[i][1]), "r"(a[i][2]), "r"(a[i][3]),   \
                    "r"(b[j][0]), "r"(b[j][1]));                              \
    }                                                                          \
} while (0)

    // prologue: fill STAGES-1 stages
#pragma unroll
    for (int s = 0; s < STAGES - 1; s++) {
        if (s < nk) LOADC(kbeg + s, s);
        asm volatile("cp.async.commit_group;\n");
    }

    for (int i = 0; i < nk; i++) {
        int st = i & (STAGES - 1);
        asm volatile("cp.async.wait_group %0;\n" :: "n"(STAGES - 2));
        __syncthreads();
        int inext = i + STAGES - 1;
        if (inext < nk) LOADC(kbeg + inext, inext & (STAGES - 1));
        asm volatile("cp.async.commit_group;\n");
        COMPUTEC(st);
    }

    // epilogue: raw partial (scale applied in reduce)
#pragma unroll
    for (int i = 0; i < 4; i++) {
        int row0 = m0 + wm + i * 16 + (lane >> 2);
#pragma unroll
        for (int j = 0; j < 4; j++) {
            int col = n0 + wn + j * 8 + (lane & 3) * 2;
            if (row0 < M) {
                float2 o = make_float2(c[i][j][0], c[i][j][1]);
                *reinterpret_cast<float2*>(&C[(size_t)row0 * N + col]) = o;
            }
            if (row0 + 8 < M) {
                float2 o = make_float2(c[i][j][2], c[i][j][3]);
                *reinterpret_cast<float2*>(&C[(size_t)(row0 + 8) * N + col]) = o;
            }
        }
    }
}

// ---------------------------------------------------------------------------
// dst = (part0 + part1 + part2 + part3) * scale   (float4 vectorized)
// ---------------------------------------------------------------------------
__global__ void __launch_bounds__(256) reduce4_kernel(
    const float* __restrict__ part, float* __restrict__ dst,
    int n4, float scale)
{
    int i = blockIdx.x * 256 + threadIdx.x;
    if (i >= n4) return;
    const float4* p = reinterpret_cast<const float4*>(part);
    float4 a = p[i];
    float4 b = p[i + (size_t)n4];
    float4 c = p[i + (size_t)2 * n4];
    float4 d = p[i + (size_t)3 * n4];
    float4 o;
    o.x = (a.x + b.x + c.x + d.x) * scale;
    o.y = (a.y + b.y + c.y + d.y) * scale;
    o.z = (a.z + b.z + c.z + d.z) * scale;
    o.w = (a.w + b.w + c.w + d.w) * scale;
    reinterpret_cast<float4*>(dst)[i] = o;
}

// ---------------------------------------------------------------------------
__global__ void __launch_bounds__(128) compute_v_kernel(
    const float* __restrict__ Wh, const float* __restrict__ wt)
{
    int a = blockIdx.x * 128 + threadIdx.x;
    float acc = 0.0f;
#pragma unroll 8
    for (int c = 0; c < ATT; c++)
        acc = fmaf(wt[c], Wh[(size_t)c * ATT + a], acc);
    g_v[a] = acc;
}

__global__ void __launch_bounds__(256) compute_cst_kernel(
    const float* __restrict__ wt, const float* __restrict__ bh,
    const float* __restrict__ bt)
{
    __shared__ float red[256];
    float acc = 0.0f;
    for (int i = threadIdx.x; i < ATT; i += 256)
        acc = fmaf(wt[i], bh[i], acc);
    red[threadIdx.x] = acc;
    __syncthreads();
    for (int s = 128; s > 0; s >>= 1) {
        if (threadIdx.x < s) red[threadIdx.x] += red[threadIdx.x + s];
        __syncthreads();
    }
    if (threadIdx.x == 0) g_cst = red[0] + bt[0];
}

// ---------------------------------------------------------------------------
// alpha[b,l,p] = sum_a tanh(p1*p2)*v[a] + cst ;  tanh = 1 - 2/(exp2(arg)+1)
// ---------------------------------------------------------------------------
__global__ void __launch_bounds__(256) bilinear_tanh_kernel(
    float* __restrict__ out)
{
    __shared__ float p1s[128][17];
    __shared__ float p2s[128][17];
    __shared__ float vs[128];

    const int b  = blockIdx.z;
    const int l0 = blockIdx.y * 16;
    const int p0 = blockIdx.x * 16;
    const int t  = threadIdx.x;
    const int tx = t & 15;
    const int ty = t >> 4;

    const float* __restrict__ p1b = g_p1 + ((size_t)b * P_ + p0) * ATT;
    const float* __restrict__ p2b = g_p2 + ((size_t)b * L_ + l0) * ATT;

    float acc = 0.0f;

    for (int a0 = 0; a0 < ATT; a0 += 128) {
        __syncthreads();
        for (int i = t; i < 16 * 128; i += 256) {
            int r = i >> 7;
            int a = i & 127;
            float v1 = 0.0f;
            if (p0 + r < P_) v1 = p1b[(size_t)r * ATT + a0 + a];
            p1s[a][r] = v1;
            p2s[a][r] = p2b[(size_t)r * ATT + a0 + a];
        }
        if (t < 128) vs[t] = g_v[a0 + t];
        __syncthreads();

#pragma unroll 8
        for (int j = 0; j < 128; j++) {
            float arg = p1s[j][tx] * p2s[j][ty];
            float e;
            asm("ex2.approx.f32 %0, %1;" : "=f"(e) : "f"(arg));
            float r;
            asm("rcp.approx.f32 %0, %1;" : "=f"(r) : "f"(e + 1.0f));
            acc = fmaf(fmaf(-2.0f, r, 1.0f), vs[j], acc);
        }
    }

    int p = p0 + tx;
    int l = l0 + ty;
    if (p < P_)
        out[((size_t)b * L_ + l) * P_ + p] = acc + g_cst;
}

// ---------------------------------------------------------------------------
extern "C" void kernel_launch(void* const* d_in, const int* in_sizes, int n_in,
                              void* d_out, int out_size)
{
    const float* x1 = (const float*)d_in[0];
    const float* x2 = (const float*)d_in[1];
    const float* W1 = (const float*)d_in[2];
    const float* W2 = (const float*)d_in[3];
    const float* Wh = (const float*)d_in[4];
    const float* bh = (const float*)d_in[5];
    const float* wt = (const float*)d_in[6];
    const float* bt = (const float*)d_in[7];
    float* out = (float*)d_out;

    void *p1_ptr, *p2_ptr, *p1p_ptr, *p2p_ptr, *a1_ptr, *b1_ptr, *a2_ptr, *b2_ptr;
    cudaGetSymbolAddress(&p1_ptr, g_p1);
    cudaGetSymbolAddress(&p2_ptr, g_p2);
    cudaGetSymbolAddress(&p1p_ptr, g_p1part);
    cudaGetSymbolAddress(&p2p_ptr, g_p2part);
    cudaGetSymbolAddress(&a1_ptr, g_a1);
    cudaGetSymbolAddress(&b1_ptr, g_b1);
    cudaGetSymbolAddress(&a2_ptr, g_a2);
    cudaGetSymbolAddress(&b2_ptr, g_b2);

    cudaFuncSetAttribute(mma_gemm_nt_ms,
                         cudaFuncAttributeMaxDynamicSharedMemorySize, DSMEM);

    // zero K-pad of gemm2 operands (900..928 per row)
    cudaMemsetAsync(a2_ptr, 0, (size_t)M2 * K2CAT * sizeof(__nv_bfloat16));
    cudaMemsetAsync(b2_ptr, 0, (size_t)ATT * K2CAT * sizeof(__nv_bfloat16));

    // split + concat prep
    {
        int t4 = M1 * (D1 / 4);
        split_cat_kernel<<<(t4 + 255) / 256, 256>>>(x1, (__nv_bfloat16*)a1_ptr,
                                                    t4, D1 / 4, D1, K1CAT, 0);
    }
    {
        int t4 = ATT * (D1 / 4);
        split_cat_kernel<<<(t4 + 255) / 256, 256>>>(W1, (__nv_bfloat16*)b1_ptr,
                                                    t4, D1 / 4, D1, K1CAT, 1);
    }
    {
        int t4 = M2 * (D2 / 4);
        split_cat_kernel<<<(t4 + 255) / 256, 256>>>(x2, (__nv_bfloat16*)a2_ptr,
                                                    t4, D2 / 4, D2, K2CAT, 0);
    }
    {
        int t4 = ATT * (D2 / 4);
        split_cat_kernel<<<(t4 + 255) / 256, 256>>>(W2, (__nv_bfloat16*)b2_ptr,
                                                    t4, D2 / 4, D2, K2CAT, 1);
    }

    // GEMM1 partials: M=1568, N=1024, 192 chunks over 4 K-splits
    {
        dim3 grid(ATT / 128, (M1 + 127) / 128, KSPLIT);
        mma_gemm_nt_ms<<<grid, 256, DSMEM>>>(
            (const __nv_bfloat16*)a1_ptr, (const __nv_bfloat16*)b1_ptr,
            (float*)p1p_ptr, M1, ATT, K1CAT, NK1, CPS1);
    }
    // GEMM2 partials: M=640, 29 chunks over 4 K-splits (8,8,8,5)
    {
        dim3 grid(ATT / 128, (M2 + 127) / 128, KSPLIT);
        mma_gemm_nt_ms<<<grid, 256, DSMEM>>>(
            (const __nv_bfloat16*)a2_ptr, (const __nv_bfloat16*)b2_ptr,
            (float*)p2p_ptr, M2, ATT, K2CAT, NK2, CPS2);
    }

    // reduce partials (apply final scales here)
    {
        int n4 = M1 * ATT / 4;
        reduce4_kernel<<<(n4 + 255) / 256, 256>>>((const float*)p1p_ptr,
                                                  (float*)p1_ptr, n4, 1.0f);
    }
    {
        int n4 = M2 * ATT / 4;
        reduce4_kernel<<<(n4 + 255) / 256, 256>>>((const float*)p2p_ptr,
                                                  (float*)p2_ptr, n4, TWO_LOG2E);
    }

    compute_v_kernel<<<ATT / 128, 128>>>(Wh, wt);
    compute_cst_kernel<<<1, 256>>>(wt, bh, bt);

    {
        dim3 grid((P_ + 15) / 16, L_ / 16, B_);
        bilinear_tanh_kernel<<<grid, 256>>>(out);
    }
}

// round 10
// speedup vs baseline: 1.3965x; 1.0133x over previous
#include <cuda_runtime.h>
#include <cuda_bf16.h>
#include <cstddef>
#include <cstdint>

#define B_   8
#define P_   196
#define L_   80
#define D1   2048
#define D2   300
#define ATT  1024
#define TWO_LOG2E 2.8853900817779268f

#define M1   (B_ * P_)      // 1568
#define M2   (B_ * L_)      // 640
#define K1CAT (3 * D1)      // 6144
#define K2CAT 928           // 3*300=900 padded to 928

#define KSPLIT 4
#define NK1    (K1CAT / 32)         // 192 chunks
#define CPS1   (NK1 / KSPLIT)       // 48
#define NK2    (K2CAT / 32)         // 29 chunks
#define CPS2   8                    // 8,8,8,5

// ---------------- scratch (no allocations allowed) ----------------
__device__ float g_p1[M1 * ATT];
__device__ float g_p2[M2 * ATT];
__device__ float g_p1part[(size_t)KSPLIT * M1 * ATT];
__device__ float g_p2part[(size_t)KSPLIT * M2 * ATT];
__device__ float g_v[ATT];
__device__ float g_cst;
__device__ __nv_bfloat16 g_a1[(size_t)M1 * K1CAT];
__device__ __nv_bfloat16 g_b1[(size_t)ATT * K1CAT];
__device__ __nv_bfloat16 g_a2[(size_t)M2 * K2CAT];
__device__ __nv_bfloat16 g_b2[(size_t)ATT * K2CAT];

// ---------------------------------------------------------------------------
// Split fp32 -> (hi, lo) bf16, K-concatenated: A:[hi|lo|hi]  B:[hi|hi|lo]
// ---------------------------------------------------------------------------
__global__ void __launch_bounds__(256) split_cat_kernel(
    const float* __restrict__ src, __nv_bfloat16* __restrict__ dst,
    int total4, int Kq, int K, int Kcat, int bmode)
{
    int i = blockIdx.x * 256 + threadIdx.x;
    if (i >= total4) return;
    int r = i / Kq;
    int k = (i - r * Kq) * 4;

    float4 x = *reinterpret_cast<const float4*>(src + (size_t)r * K + k);
    float xs[4] = {x.x, x.y, x.z, x.w};
    unsigned short hs[4], ls[4];
#pragma unroll
    for (int j = 0; j < 4; j++) {
        __nv_bfloat16 h = __float2bfloat16(xs[j]);
        __nv_bfloat16 l = __float2bfloat16(xs[j] - __bfloat162float(h));
        hs[j] = __bfloat16_as_ushort(h);
        ls[j] = __bfloat16_as_ushort(l);
    }
    uint2 H, L;
    H.x = (unsigned)hs[0] | ((unsigned)hs[1] << 16);
    H.y = (unsigned)hs[2] | ((unsigned)hs[3] << 16);
    L.x = (unsigned)ls[0] | ((unsigned)ls[1] << 16);
    L.y = (unsigned)ls[2] | ((unsigned)ls[3] << 16);

    size_t base = (size_t)r * Kcat + k;
    if (bmode == 0) {
        *reinterpret_cast<uint2*>(dst + base)         = H;
        *reinterpret_cast<uint2*>(dst + base + K)     = L;
        *reinterpret_cast<uint2*>(dst + base + 2 * K) = H;
    } else {
        *reinterpret_cast<uint2*>(dst + base)         = H;
        *reinterpret_cast<uint2*>(dst + base + K)     = H;
        *reinterpret_cast<uint2*>(dst + base + 2 * K) = L;
    }
}

// ---------------------------------------------------------------------------
// bf16 MMA GEMM NT, 5-stage cp.async pipeline, split-K partial outputs.
// Block 128x128, 256 thr (8 warps 2x4), warp 64x32, K-chunk 32.
// __launch_bounds__(256,2): force <=128 regs so 2 CTAs/SM co-reside.
// ---------------------------------------------------------------------------
#define STAGES 5
#define SROW 40                       // bf16 per smem row (80B)
#define STG_B (128 * SROW * 2)        // 10240 B per operand-stage
#define DSMEM (2 * STAGES * STG_B)    // 102400 B

__global__ void __launch_bounds__(256, 2) mma_gemm_nt_ms(
    const __nv_bfloat16* __restrict__ A, const __nv_bfloat16* __restrict__ Bm,
    float* __restrict__ Cpart, int M, int N, int Kld,
    int total_chunks, int chunks_per_split)
{
    extern __shared__ __align__(16) char smem_raw[];
    const uint32_t sA0 = (uint32_t)__cvta_generic_to_shared(smem_raw);
    const uint32_t sB0 = sA0 + STAGES * STG_B;

    const int t    = threadIdx.x;
    const int lane = t & 31;
    const int warp = t >> 5;
    const int wm   = (warp >> 2) * 64;
    const int wn   = (warp & 3) * 32;
    const int m0   = blockIdx.y * 128;
    const int n0   = blockIdx.x * 128;
    const int ks   = blockIdx.z;
    const int kbeg = ks * chunks_per_split;
    int nk = total_chunks - kbeg;
    if (nk > chunks_per_split) nk = chunks_per_split;
    float* __restrict__ C = Cpart + (size_t)ks * M * N;

    float c[4][4][4];
#pragma unroll
    for (int i = 0; i < 4; i++)
#pragma unroll
        for (int j = 0; j < 4; j++)
#pragma unroll
            for (int r = 0; r < 4; r++) c[i][j][r] = 0.0f;

    const int lrow0 = t >> 2;
    const int lseg  = (t & 3) * 8;

#define LOADC(kc, st) do {                                                    \
    _Pragma("unroll")                                                         \
    for (int it = 0; it < 2; it++) {                                          \
        int row = lrow0 + it * 64;                                            \
        int ga  = m0 + row;                                                   \
        const __nv_bfloat16* srcA = A + (size_t)ga * Kld + (kc) * 32 + lseg;  \
        uint32_t dstA = sA0 + (st) * STG_B + row * (SROW * 2) + lseg * 2;     \
        int bytesA = (ga < M) ? 16 : 0;                                       \
        asm volatile("cp.async.cg.shared.global [%0], [%1], 16, %2;\n"        \
                     :: "r"(dstA), "l"(srcA), "r"(bytesA));                   \
        const __nv_bfloat16* srcB = Bm + (size_t)(n0 + row) * Kld + (kc) * 32 + lseg; \
        uint32_t dstB = sB0 + (st) * STG_B + row * (SROW * 2) + lseg * 2;     \
        asm volatile("cp.async.cg.shared.global [%0], [%1], 16;\n"            \
                     :: "r"(dstB), "l"(srcB));                                \
    }                                                                          \
} while (0)

#define COMPUTEC(st) do {                                                     \
    _Pragma("unroll")                                                         \
    for (int ksub = 0; ksub < 2; ksub++) {                                    \
        int koff = ksub * 16;                                                 \
        uint32_t a[4][4];                                                     \
        _Pragma("unroll")                                                     \
        for (int i = 0; i < 4; i++) {                                         \
            uint32_t addr = sA0 + (st) * STG_B                                \
                + (wm + i * 16 + (lane & 15)) * (SROW * 2)                    \
                + ((lane >> 4) * 8 + koff) * 2;                               \
            asm volatile("ldmatrix.sync.aligned.m8n8.x4.shared.b16 "          \
                         "{%0,%1,%2,%3}, [%4];\n"                             \
                         : "=r"(a[i][0]), "=r"(a[i][1]),                      \
                           "=r"(a[i][2]), "=r"(a[i][3]) : "r"(addr));         \
        }                                                                     \
        uint32_t b[4][2];                                                     \
        _Pragma("unroll")                                                     \
        for (int j2 = 0; j2 < 2; j2++) {                                      \
            uint32_t addr = sB0 + (st) * STG_B                                \
                + (wn + j2 * 16 + (lane & 15)) * (SROW * 2)                   \
                + ((lane >> 4) * 8 + koff) * 2;                               \
            uint32_t r0, r1, r2, r3;                                          \
            asm volatile("ldmatrix.sync.aligned.m8n8.x4.shared.b16 "          \
                         "{%0,%1,%2,%3}, [%4];\n"                             \
                         : "=r"(r0), "=r"(r1), "=r"(r2), "=r"(r3)             \
                         : "r"(addr));                                        \
            b[2 * j2][0] = r0; b[2 * j2 + 1][0] = r1;                         \
            b[2 * j2][1] = r2; b[2 * j2 + 1][1] = r3;                         \
        }                                                                     \
        _Pragma("unroll")                                                     \
        for (int i = 0; i < 4; i++)                                           \
            _Pragma("unroll")                                                 \
            for (int j = 0; j < 4; j++)                                       \
                asm volatile(                                                 \
                  "mma.sync.aligned.m16n8k16.row.col.f32.bf16.bf16.f32 "      \
                  "{%0,%1,%2,%3}, {%4,%5,%6,%7}, {%8,%9}, {%0,%1,%2,%3};\n"   \
                  : "+f"(c[i][j][0]), "+f"(c[i][j][1]),                       \
                    "+f"(c[i][j][2]), "+f"(c[i][j][3])                        \
                  : "r"(a[i][0]), "r"(a[i][1]), "r"(a[i][2]), "r"(a[i][3]),   \
                    "r"(b[j][0]), "r"(b[j][1]));                              \
    }                                                                          \
} while (0)

    // prologue: fill STAGES-1 = 4 stages
#pragma unroll
    for (int s = 0; s < STAGES - 1; s++) {
        if (s < nk) LOADC(kbeg + s, s);
        asm volatile("cp.async.commit_group;\n");
    }

    int stc = 0;             // stage holding chunk i
    int stl = STAGES - 1;    // stage receiving chunk i + STAGES-1
    for (int i = 0; i < nk; i++) {
        asm volatile("cp.async.wait_group %0;\n" :: "n"(STAGES - 2));
        __syncthreads();
        int j = i + STAGES - 1;
        if (j < nk) LOADC(kbeg + j, stl);
        asm volatile("cp.async.commit_group;\n");
        COMPUTEC(stc);
        stc = (stc + 1 == STAGES) ? 0 : stc + 1;
        stl = (stl + 1 == STAGES) ? 0 : stl + 1;
    }

    // epilogue: raw partial (scale applied in reduce)
#pragma unroll
    for (int i = 0; i < 4; i++) {
        int row0 = m0 + wm + i * 16 + (lane >> 2);
#pragma unroll
        for (int j = 0; j < 4; j++) {
            int col = n0 + wn + j * 8 + (lane & 3) * 2;
            if (row0 < M) {
                float2 o = make_float2(c[i][j][0], c[i][j][1]);
                *reinterpret_cast<float2*>(&C[(size_t)row0 * N + col]) = o;
            }
            if (row0 + 8 < M) {
                float2 o = make_float2(c[i][j][2], c[i][j][3]);
                *reinterpret_cast<float2*>(&C[(size_t)(row0 + 8) * N + col]) = o;
            }
        }
    }
}

// ---------------------------------------------------------------------------
// Fused reduce: y==0 -> p1 (n4a, scale 1), y==1 -> p2 (n4b, scale 2log2e)
// ---------------------------------------------------------------------------
__global__ void __launch_bounds__(256) reduce4_both_kernel(
    const float* __restrict__ partA, float* __restrict__ dstA, int n4a,
    const float* __restrict__ partB, float* __restrict__ dstB, int n4b)
{
    int i = blockIdx.x * 256 + threadIdx.x;
    const float* part;
    float* dst;
    int n4;
    float scale;
    if (blockIdx.y == 0) { part = partA; dst = dstA; n4 = n4a; scale = 1.0f; }
    else                 { part = partB; dst = dstB; n4 = n4b; scale = TWO_LOG2E; }
    if (i >= n4) return;
    const float4* p = reinterpret_cast<const float4*>(part);
    float4 a = p[i];
    float4 b = p[i + (size_t)n4];
    float4 c = p[i + (size_t)2 * n4];
    float4 d = p[i + (size_t)3 * n4];
    float4 o;
    o.x = (a.x + b.x + c.x + d.x) * scale;
    o.y = (a.y + b.y + c.y + d.y) * scale;
    o.z = (a.z + b.z + c.z + d.z) * scale;
    o.w = (a.w + b.w + c.w + d.w) * scale;
    reinterpret_cast<float4*>(dst)[i] = o;
}

// ---------------------------------------------------------------------------
// blocks 0..7: v[a] = sum_c wt[c]*Wh[c][a] ; block 8: cst = dot(wt,bh)+bt
// ---------------------------------------------------------------------------
__global__ void __launch_bounds__(128) v_and_cst_kernel(
    const float* __restrict__ Wh, const float* __restrict__ wt,
    const float* __restrict__ bh, const float* __restrict__ bt)
{
    if (blockIdx.x < 8) {
        int a = blockIdx.x * 128 + threadIdx.x;
        float acc = 0.0f;
#pragma unroll 8
        for (int c = 0; c < ATT; c++)
            acc = fmaf(wt[c], Wh[(size_t)c * ATT + a], acc);
        g_v[a] = acc;
    } else {
        __shared__ float red[128];
        float acc = 0.0f;
        for (int i = threadIdx.x; i < ATT; i += 128)
            acc = fmaf(wt[i], bh[i], acc);
        red[threadIdx.x] = acc;
        __syncthreads();
        for (int s = 64; s > 0; s >>= 1) {
            if (threadIdx.x < s) red[threadIdx.x] += red[threadIdx.x + s];
            __syncthreads();
        }
        if (threadIdx.x == 0) g_cst = red[0] + bt[0];
    }
}

// ---------------------------------------------------------------------------
// alpha[b,l,p] = sum_a tanh(p1*p2)*v[a] + cst ;  tanh = 1 - 2/(exp2(arg)+1)
// ---------------------------------------------------------------------------
__global__ void __launch_bounds__(256) bilinear_tanh_kernel(
    float* __restrict__ out)
{
    __shared__ float p1s[128][17];
    __shared__ float p2s[128][17];
    __shared__ float vs[128];

    const int b  = blockIdx.z;
    const int l0 = blockIdx.y * 16;
    const int p0 = blockIdx.x * 16;
    const int t  = threadIdx.x;
    const int tx = t & 15;
    const int ty = t >> 4;

    const float* __restrict__ p1b = g_p1 + ((size_t)b * P_ + p0) * ATT;
    const float* __restrict__ p2b = g_p2 + ((size_t)b * L_ + l0) * ATT;

    float acc = 0.0f;

    for (int a0 = 0; a0 < ATT; a0 += 128) {
        __syncthreads();
        for (int i = t; i < 16 * 128; i += 256) {
            int r = i >> 7;
            int a = i & 127;
            float v1 = 0.0f;
            if (p0 + r < P_) v1 = p1b[(size_t)r * ATT + a0 + a];
            p1s[a][r] = v1;
            p2s[a][r] = p2b[(size_t)r * ATT + a0 + a];
        }
        if (t < 128) vs[t] = g_v[a0 + t];
        __syncthreads();

#pragma unroll 8
        for (int j = 0; j < 128; j++) {
            float arg = p1s[j][tx] * p2s[j][ty];
            float e;
            asm("ex2.approx.f32 %0, %1;" : "=f"(e) : "f"(arg));
            float r;
            asm("rcp.approx.f32 %0, %1;" : "=f"(r) : "f"(e + 1.0f));
            acc = fmaf(fmaf(-2.0f, r, 1.0f), vs[j], acc);
        }
    }

    int p = p0 + tx;
    int l = l0 + ty;
    if (p < P_)
        out[((size_t)b * L_ + l) * P_ + p] = acc + g_cst;
}

// ---------------------------------------------------------------------------
extern "C" void kernel_launch(void* const* d_in, const int* in_sizes, int n_in,
                              void* d_out, int out_size)
{
    const float* x1 = (const float*)d_in[0];
    const float* x2 = (const float*)d_in[1];
    const float* W1 = (const float*)d_in[2];
    const float* W2 = (const float*)d_in[3];
    const float* Wh = (const float*)d_in[4];
    const float* bh = (const float*)d_in[5];
    const float* wt = (const float*)d_in[6];
    const float* bt = (const float*)d_in[7];
    float* out = (float*)d_out;

    void *p1_ptr, *p2_ptr, *p1p_ptr, *p2p_ptr, *a1_ptr, *b1_ptr, *a2_ptr, *b2_ptr;
    cudaGetSymbolAddress(&p1_ptr, g_p1);
    cudaGetSymbolAddress(&p2_ptr, g_p2);
    cudaGetSymbolAddress(&p1p_ptr, g_p1part);
    cudaGetSymbolAddress(&p2p_ptr, g_p2part);
    cudaGetSymbolAddress(&a1_ptr, g_a1);
    cudaGetSymbolAddress(&b1_ptr, g_b1);
    cudaGetSymbolAddress(&a2_ptr, g_a2);
    cudaGetSymbolAddress(&b2_ptr, g_b2);

    cudaFuncSetAttribute(mma_gemm_nt_ms,
                         cudaFuncAttributeMaxDynamicSharedMemorySize, DSMEM);

    // launches 0,1: zero K-pad of gemm2 operands (900..928 per row)
    cudaMemsetAsync(a2_ptr, 0, (size_t)M2 * K2CAT * sizeof(__nv_bfloat16));
    cudaMemsetAsync(b2_ptr, 0, (size_t)ATT * K2CAT * sizeof(__nv_bfloat16));

    // launches 2,3,4: splits needed before GEMM1 (+x2 filler so GEMM1 = idx 5)
    {
        int t4 = M1 * (D1 / 4);
        split_cat_kernel<<<(t4 + 255) / 256, 256>>>(x1, (__nv_bfloat16*)a1_ptr,
                                                    t4, D1 / 4, D1, K1CAT, 0);
    }
    {
        int t4 = ATT * (D1 / 4);
        split_cat_kernel<<<(t4 + 255) / 256, 256>>>(W1, (__nv_bfloat16*)b1_ptr,
                                                    t4, D1 / 4, D1, K1CAT, 1);
    }
    {
        int t4 = M2 * (D2 / 4);
        split_cat_kernel<<<(t4 + 255) / 256, 256>>>(x2, (__nv_bfloat16*)a2_ptr,
                                                    t4, D2 / 4, D2, K2CAT, 0);
    }

    // launch 5 (ncu-profiled slot): GEMM1 partials
    {
        dim3 grid(ATT / 128, (M1 + 127) / 128, KSPLIT);
        mma_gemm_nt_ms<<<grid, 256, DSMEM>>>(
            (const __nv_bfloat16*)a1_ptr, (const __nv_bfloat16*)b1_ptr,
            (float*)p1p_ptr, M1, ATT, K1CAT, NK1, CPS1);
    }

    // launch 6: W2 split ; launch 7: GEMM2
    {
        int t4 = ATT * (D2 / 4);
        split_cat_kernel<<<(t4 + 255) / 256, 256>>>(W2, (__nv_bfloat16*)b2_ptr,
                                                    t4, D2 / 4, D2, K2CAT, 1);
    }
    {
        dim3 grid(ATT / 128, (M2 + 127) / 128, KSPLIT);
        mma_gemm_nt_ms<<<grid, 256, DSMEM>>>(
            (const __nv_bfloat16*)a2_ptr, (const __nv_bfloat16*)b2_ptr,
            (float*)p2p_ptr, M2, ATT, K2CAT, NK2, CPS2);
    }

    // launch 8: fused reduce of both partial sets
    {
        int n4a = M1 * ATT / 4;
        int n4b = M2 * ATT / 4;
        dim3 grid((n4a + 255) / 256, 2);
        reduce4_both_kernel<<<grid, 256>>>((const float*)p1p_ptr, (float*)p1_ptr,
                                           n4a,
                                           (const float*)p2p_ptr, (float*)p2_ptr,
                                           n4b);
    }

    // launch 9: v + cst fused
    v_and_cst_kernel<<<9, 128>>>(Wh, wt, bh, bt);

    // launch 10: main fused tanh-bilinear reduction
    {
        dim3 grid((P_ + 15) / 16, L_ / 16, B_);
        bilinear_tanh_kernel<<<grid, 256>>>(out);
    }
}

// round 12
// speedup vs baseline: 1.5834x; 1.1338x over previous
#include <cuda_runtime.h>
#include <cuda_fp16.h>
#include <cstddef>
#include <cstdint>

#define B_   8
#define P_   196
#define L_   80
#define D1   2048
#define D2   300
#define ATT  1024
#define TWO_LOG2E 2.8853900817779268f

#define M1   (B_ * P_)      // 1568
#define M2   (B_ * L_)      // 640
#define K1CAT (2 * D1)      // 4096  (fp16 2-term split)
#define K2CAT 608           // 2*300=600 padded to 608 (19 chunks of 32)

#define KSPLIT 3
#define NK1    (K1CAT / 32)         // 128 chunks
#define CPS1   43                   // 43,43,42
#define NK2    (K2CAT / 32)         // 19 chunks
#define CPS2   7                    // 7,7,5

// ---------------- scratch (no allocations allowed) ----------------
__device__ float g_p1[M1 * ATT];
__device__ float g_p2[M2 * ATT];
__device__ float g_p1part[(size_t)KSPLIT * M1 * ATT];
__device__ float g_p2part[(size_t)KSPLIT * M2 * ATT];
__device__ float g_v[ATT];
__device__ float g_cst;
__device__ __half g_a1[(size_t)M1 * K1CAT];
__device__ __half g_b1[(size_t)ATT * K1CAT];
__device__ __half g_a2[(size_t)M2 * K2CAT];
__device__ __half g_b2[(size_t)ATT * K2CAT];

// ---------------------------------------------------------------------------
// Split fp32 -> (hi, lo) fp16, K-concatenated: A:[hi|lo]  B:[hi|hi]
// Acat.Bcat = Ah.Bh + Al.Bh = A.Bh  (error = A.Bl ~ 2^-12 rel)
// ---------------------------------------------------------------------------
__global__ void __launch_bounds__(256) split_cat_kernel(
    const float* __restrict__ src, __half* __restrict__ dst,
    int total4, int Kq, int K, int Kcat, int bmode)
{
    int i = blockIdx.x * 256 + threadIdx.x;
    if (i >= total4) return;
    int r = i / Kq;
    int k = (i - r * Kq) * 4;

    float4 x = *reinterpret_cast<const float4*>(src + (size_t)r * K + k);
    float xs[4] = {x.x, x.y, x.z, x.w};
    unsigned short hs[4], ls[4];
#pragma unroll
    for (int j = 0; j < 4; j++) {
        __half h = __float2half_rn(xs[j]);
        __half l = __float2half_rn(xs[j] - __half2float(h));
        hs[j] = __half_as_ushort(h);
        ls[j] = __half_as_ushort(l);
    }
    uint2 H, L;
    H.x = (unsigned)hs[0] | ((unsigned)hs[1] << 16);
    H.y = (unsigned)hs[2] | ((unsigned)hs[3] << 16);
    L.x = (unsigned)ls[0] | ((unsigned)ls[1] << 16);
    L.y = (unsigned)ls[2] | ((unsigned)ls[3] << 16);

    size_t base = (size_t)r * Kcat + k;
    if (bmode == 0) {
        *reinterpret_cast<uint2*>(dst + base)     = H;
        *reinterpret_cast<uint2*>(dst + base + K) = L;
    } else {
        *reinterpret_cast<uint2*>(dst + base)     = H;
        *reinterpret_cast<uint2*>(dst + base + K) = H;
    }
}

// ---------------------------------------------------------------------------
// fp16 MMA GEMM NT, 5-stage cp.async pipeline, split-K partial outputs.
// Block 128x128, 256 thr (8 warps 2x4), warp 64x32, K-chunk 32.
// __launch_bounds__(256,2): force <=128 regs so 2 CTAs/SM co-reside.
// ---------------------------------------------------------------------------
#define STAGES 5
#define SROW 40                       // fp16 per smem row (80B)
#define STG_B (128 * SROW * 2)        // 10240 B per operand-stage
#define DSMEM (2 * STAGES * STG_B)    // 102400 B

__global__ void __launch_bounds__(256, 2) mma_gemm_nt_ms(
    const __half* __restrict__ A, const __half* __restrict__ Bm,
    float* __restrict__ Cpart, int M, int N, int Kld,
    int total_chunks, int chunks_per_split)
{
    extern __shared__ __align__(16) char smem_raw[];
    const uint32_t sA0 = (uint32_t)__cvta_generic_to_shared(smem_raw);
    const uint32_t sB0 = sA0 + STAGES * STG_B;

    const int t    = threadIdx.x;
    const int lane = t & 31;
    const int warp = t >> 5;
    const int wm   = (warp >> 2) * 64;
    const int wn   = (warp & 3) * 32;
    const int m0   = blockIdx.y * 128;
    const int n0   = blockIdx.x * 128;
    const int ks   = blockIdx.z;
    const int kbeg = ks * chunks_per_split;
    int nk = total_chunks - kbeg;
    if (nk > chunks_per_split) nk = chunks_per_split;
    float* __restrict__ C = Cpart + (size_t)ks * M * N;

    float c[4][4][4];
#pragma unroll
    for (int i = 0; i < 4; i++)
#pragma unroll
        for (int j = 0; j < 4; j++)
#pragma unroll
            for (int r = 0; r < 4; r++) c[i][j][r] = 0.0f;

    const int lrow0 = t >> 2;
    const int lseg  = (t & 3) * 8;

#define LOADC(kc, st) do {                                                    \
    _Pragma("unroll")                                                         \
    for (int it = 0; it < 2; it++) {                                          \
        int row = lrow0 + it * 64;                                            \
        int ga  = m0 + row;                                                   \
        const __half* srcA = A + (size_t)ga * Kld + (kc) * 32 + lseg;         \
        uint32_t dstA = sA0 + (st) * STG_B + row * (SROW * 2) + lseg * 2;     \
        int bytesA = (ga < M) ? 16 : 0;                                       \
        asm volatile("cp.async.cg.shared.global [%0], [%1], 16, %2;\n"        \
                     :: "r"(dstA), "l"(srcA), "r"(bytesA));                   \
        const __half* srcB = Bm + (size_t)(n0 + row) * Kld + (kc) * 32 + lseg; \
        uint32_t dstB = sB0 + (st) * STG_B + row * (SROW * 2) + lseg * 2;     \
        asm volatile("cp.async.cg.shared.global [%0], [%1], 16;\n"            \
                     :: "r"(dstB), "l"(srcB));                                \
    }                                                                          \
} while (0)

#define COMPUTEC(st) do {                                                     \
    _Pragma("unroll")                                                         \
    for (int ksub = 0; ksub < 2; ksub++) {                                    \
        int koff = ksub * 16;                                                 \
        uint32_t a[4][4];                                                     \
        _Pragma("unroll")                                                     \
        for (int i = 0; i < 4; i++) {                                         \
            uint32_t addr = sA0 + (st) * STG_B                                \
                + (wm + i * 16 + (lane & 15)) * (SROW * 2)                    \
                + ((lane >> 4) * 8 + koff) * 2;                               \
            asm volatile("ldmatrix.sync.aligned.m8n8.x4.shared.b16 "          \
                         "{%0,%1,%2,%3}, [%4];\n"                             \
                         : "=r"(a[i][0]), "=r"(a[i][1]),                      \
                           "=r"(a[i][2]), "=r"(a[i][3]) : "r"(addr));         \
        }                                                                     \
        uint32_t b[4][2];                                                     \
        _Pragma("unroll")                                                     \
        for (int j2 = 0; j2 < 2; j2++) {                                      \
            uint32_t addr = sB0 + (st) * STG_B                                \
                + (wn + j2 * 16 + (lane & 15)) * (SROW * 2)                   \
                + ((lane >> 4) * 8 + koff) * 2;                               \
            uint32_t r0, r1, r2, r3;                                          \
            asm volatile("ldmatrix.sync.aligned.m8n8.x4.shared.b16 "          \
                         "{%0,%1,%2,%3}, [%4];\n"                             \
                         : "=r"(r0), "=r"(r1), "=r"(r2), "=r"(r3)             \
                         : "r"(addr));                                        \
            b[2 * j2][0] = r0; b[2 * j2 + 1][0] = r1;                         \
            b[2 * j2][1] = r2; b[2 * j2 + 1][1] = r3;                         \
        }                                                                     \
        _Pragma("unroll")                                                     \
        for (int i = 0; i < 4; i++)                                           \
            _Pragma("unroll")                                                 \
            for (int j = 0; j < 4; j++)                                       \
                asm volatile(                                                 \
                  "mma.sync.aligned.m16n8k16.row.col.f32.f16.f16.f32 "        \
                  "{%0,%1,%2,%3}, {%4,%5,%6,%7}, {%8,%9}, {%0,%1,%2,%3};\n"   \
                  : "+f"(c[i][j][0]), "+f"(c[i][j][1]),                       \
                    "+f"(c[i][j][2]), "+f"(c[i][j][3])                        \
                  : "r"(a[i][0]), "r"(a[i][1]), "r"(a[i][2]), "r"(a[i][3]),   \
                    "r"(b[j][0]), "r"(b[j][1]));                              \
    }                                                                          \
} while (0)

    // prologue: fill STAGES-1 = 4 stages
#pragma unroll
    for (int s = 0; s < STAGES - 1; s++) {
        if (s < nk) LOADC(kbeg + s, s);
        asm volatile("cp.async.commit_group;\n");
    }

    int stc = 0;             // stage holding chunk i
    int stl = STAGES - 1;    // stage receiving chunk i + STAGES-1
    for (int i = 0; i < nk; i++) {
        asm volatile("cp.async.wait_group %0;\n" :: "n"(STAGES - 2));
        __syncthreads();
        int j = i + STAGES - 1;
        if (j < nk) LOADC(kbeg + j, stl);
        asm volatile("cp.async.commit_group;\n");
        COMPUTEC(stc);
        stc = (stc + 1 == STAGES) ? 0 : stc + 1;
        stl = (stl + 1 == STAGES) ? 0 : stl + 1;
    }

    // epilogue: raw partial (scale applied in reduce)
#pragma unroll
    for (int i = 0; i < 4; i++) {
        int row0 = m0 + wm + i * 16 + (lane >> 2);
#pragma unroll
        for (int j = 0; j < 4; j++) {
            int col = n0 + wn + j * 8 + (lane & 3) * 2;
            if (row0 < M) {
                float2 o = make_float2(c[i][j][0], c[i][j][1]);
                *reinterpret_cast<float2*>(&C[(size_t)row0 * N + col]) = o;
            }
            if (row0 + 8 < M) {
                float2 o = make_float2(c[i][j][2], c[i][j][3]);
                *reinterpret_cast<float2*>(&C[(size_t)(row0 + 8) * N + col]) = o;
            }
        }
    }
}

// ---------------------------------------------------------------------------
// Fused reduce of 3 partials: y==0 -> p1 (scale 1), y==1 -> p2 (scale 2log2e)
// ---------------------------------------------------------------------------
__global__ void __launch_bounds__(256) reduce3_both_kernel(
    const float* __restrict__ partA, float* __restrict__ dstA, int n4a,
    const float* __restrict__ partB, float* __restrict__ dstB, int n4b)
{
    int i = blockIdx.x * 256 + threadIdx.x;
    const float* part;
    float* dst;
    int n4;
    float scale;
    if (blockIdx.y == 0) { part = partA; dst = dstA; n4 = n4a; scale = 1.0f; }
    else                 { part = partB; dst = dstB; n4 = n4b; scale = TWO_LOG2E; }
    if (i >= n4) return;
    const float4* p = reinterpret_cast<const float4*>(part);
    float4 a = p[i];
    float4 b = p[i + (size_t)n4];
    float4 c = p[i + (size_t)2 * n4];
    float4 o;
    o.x = (a.x + b.x + c.x) * scale;
    o.y = (a.y + b.y + c.y) * scale;
    o.z = (a.z + b.z + c.z) * scale;
    o.w = (a.w + b.w + c.w) * scale;
    reinterpret_cast<float4*>(dst)[i] = o;
}

// ---------------------------------------------------------------------------
// blocks 0..7: v[a] = sum_c wt[c]*Wh[c][a] ; block 8: cst = dot(wt,bh)+bt
// ---------------------------------------------------------------------------
__global__ void __launch_bounds__(128) v_and_cst_kernel(
    const float* __restrict__ Wh, const float* __restrict__ wt,
    const float* __restrict__ bh, const float* __restrict__ bt)
{
    if (blockIdx.x < 8) {
        int a = blockIdx.x * 128 + threadIdx.x;
        float acc = 0.0f;
#pragma unroll 8
        for (int c = 0; c < ATT; c++)
            acc = fmaf(wt[c], Wh[(size_t)c * ATT + a], acc);
        g_v[a] = acc;
    } else {
        __shared__ float red[128];
        float acc = 0.0f;
        for (int i = threadIdx.x; i < ATT; i += 128)
            acc = fmaf(wt[i], bh[i], acc);
        red[threadIdx.x] = acc;
        __syncthreads();
        for (int s = 64; s > 0; s >>= 1) {
            if (threadIdx.x < s) red[threadIdx.x] += red[threadIdx.x + s];
            __syncthreads();
        }
        if (threadIdx.x == 0) g_cst = red[0] + bt[0];
    }
}

// ---------------------------------------------------------------------------
// alpha[b,l,p] = sum_a tanh(p1*p2)*v[a] + cst ;  tanh = 1 - 2/(exp2(arg)+1)
// ---------------------------------------------------------------------------
__global__ void __launch_bounds__(256) bilinear_tanh_kernel(
    float* __restrict__ out)
{
    __shared__ float p1s[128][17];
    __shared__ float p2s[128][17];
    __shared__ float vs[128];

    const int b  = blockIdx.z;
    const int l0 = blockIdx.y * 16;
    const int p0 = blockIdx.x * 16;
    const int t  = threadIdx.x;
    const int tx = t & 15;
    const int ty = t >> 4;

    const float* __restrict__ p1b = g_p1 + ((size_t)b * P_ + p0) * ATT;
    const float* __restrict__ p2b = g_p2 + ((size_t)b * L_ + l0) * ATT;

    float acc = 0.0f;

    for (int a0 = 0; a0 < ATT; a0 += 128) {
        __syncthreads();
        for (int i = t; i < 16 * 128; i += 256) {
            int r = i >> 7;
            int a = i & 127;
            float v1 = 0.0f;
            if (p0 + r < P_) v1 = p1b[(size_t)r * ATT + a0 + a];
            p1s[a][r] = v1;
            p2s[a][r] = p2b[(size_t)r * ATT + a0 + a];
        }
        if (t < 128) vs[t] = g_v[a0 + t];
        __syncthreads();

#pragma unroll 8
        for (int j = 0; j < 128; j++) {
            float arg = p1s[j][tx] * p2s[j][ty];
            float e;
            asm("ex2.approx.f32 %0, %1;" : "=f"(e) : "f"(arg));
            float r;
            asm("rcp.approx.f32 %0, %1;" : "=f"(r) : "f"(e + 1.0f));
            acc = fmaf(fmaf(-2.0f, r, 1.0f), vs[j], acc);
        }
    }

    int p = p0 + tx;
    int l = l0 + ty;
    if (p < P_)
        out[((size_t)b * L_ + l) * P_ + p] = acc + g_cst;
}

// ---------------------------------------------------------------------------
extern "C" void kernel_launch(void* const* d_in, const int* in_sizes, int n_in,
                              void* d_out, int out_size)
{
    const float* x1 = (const float*)d_in[0];
    const float* x2 = (const float*)d_in[1];
    const float* W1 = (const float*)d_in[2];
    const float* W2 = (const float*)d_in[3];
    const float* Wh = (const float*)d_in[4];
    const float* bh = (const float*)d_in[5];
    const float* wt = (const float*)d_in[6];
    const float* bt = (const float*)d_in[7];
    float* out = (float*)d_out;

    void *p1_ptr, *p2_ptr, *p1p_ptr, *p2p_ptr, *a1_ptr, *b1_ptr, *a2_ptr, *b2_ptr;
    cudaGetSymbolAddress(&p1_ptr, g_p1);
    cudaGetSymbolAddress(&p2_ptr, g_p2);
    cudaGetSymbolAddress(&p1p_ptr, g_p1part);
    cudaGetSymbolAddress(&p2p_ptr, g_p2part);
    cudaGetSymbolAddress(&a1_ptr, g_a1);
    cudaGetSymbolAddress(&b1_ptr, g_b1);
    cudaGetSymbolAddress(&a2_ptr, g_a2);
    cudaGetSymbolAddress(&b2_ptr, g_b2);

    cudaFuncSetAttribute(mma_gemm_nt_ms,
                         cudaFuncAttributeMaxDynamicSharedMemorySize, DSMEM);

    // launches 0,1: zero gemm2 operand buffers (covers K-pad 600..608)
    cudaMemsetAsync(a2_ptr, 0, (size_t)M2 * K2CAT * sizeof(__half));
    cudaMemsetAsync(b2_ptr, 0, (size_t)ATT * K2CAT * sizeof(__half));

    // launches 2,3,4: splits needed before GEMM1 (x1, W1, x2)
    {
        int t4 = M1 * (D1 / 4);
        split_cat_kernel<<<(t4 + 255) / 256, 256>>>(x1, (__half*)a1_ptr,
                                                    t4, D1 / 4, D1, K1CAT, 0);
    }
    {
        int t4 = ATT * (D1 / 4);
        split_cat_kernel<<<(t4 + 255) / 256, 256>>>(W1, (__half*)b1_ptr,
                                                    t4, D1 / 4, D1, K1CAT, 1);
    }
    {
        int t4 = M2 * (D2 / 4);
        split_cat_kernel<<<(t4 + 255) / 256, 256>>>(x2, (__half*)a2_ptr,
                                                    t4, D2 / 4, D2, K2CAT, 0);
    }

    // launch 5 (ncu-profiled slot): GEMM1 partials, 312 CTAs ~ 1.05 waves
    {
        dim3 grid(ATT / 128, (M1 + 127) / 128, KSPLIT);
        mma_gemm_nt_ms<<<grid, 256, DSMEM>>>(
            (const __half*)a1_ptr, (const __half*)b1_ptr,
            (float*)p1p_ptr, M1, ATT, K1CAT, NK1, CPS1);
    }

    // launch 6: W2 split ; launch 7: GEMM2
    {
        int t4 = ATT * (D2 / 4);
        split_cat_kernel<<<(t4 + 255) / 256, 256>>>(W2, (__half*)b2_ptr,
                                                    t4, D2 / 4, D2, K2CAT, 1);
    }
    {
        dim3 grid(ATT / 128, (M2 + 127) / 128, KSPLIT);
        mma_gemm_nt_ms<<<grid, 256, DSMEM>>>(
            (const __half*)a2_ptr, (const __half*)b2_ptr,
            (float*)p2p_ptr, M2, ATT, K2CAT, NK2, CPS2);
    }

    // launch 8: fused reduce of both partial sets (3 splits each)
    {
        int n4a = M1 * ATT / 4;
        int n4b = M2 * ATT / 4;
        dim3 grid((n4a + 255) / 256, 2);
        reduce3_both_kernel<<<grid, 256>>>((const float*)p1p_ptr, (float*)p1_ptr,
                                           n4a,
                                           (const float*)p2p_ptr, (float*)p2_ptr,
                                           n4b);
    }

    // launch 9: v + cst fused
    v_and_cst_kernel<<<9, 128>>>(Wh, wt, bh, bt);

    // launch 10: main fused tanh-bilinear reduction
    {
        dim3 grid((P_ + 15) / 16, L_ / 16, B_);
        bilinear_tanh_kernel<<<grid, 256>>>(out);
    }
}

// round 13
// speedup vs baseline: 1.9108x; 1.2067x over previous
#include <cuda_runtime.h>
#include <cuda_fp16.h>
#include <cstddef>
#include <cstdint>

#define B_   8
#define P_   196
#define L_   80
#define D1   2048
#define D2   300
#define ATT  1024

#define M1   (B_ * P_)      // 1568
#define M2   (B_ * L_)      // 640
#define K1CAT (2 * D1)      // 4096  (fp16 2-term split)
#define K2CAT 608           // 2*300=600 padded to 608 (19 chunks of 32)

#define KSPLIT 2
#define NK1    (K1CAT / 32)         // 128 chunks
#define CPS1   64                   // 64,64
#define NK2    (K2CAT / 32)         // 19 chunks
#define CPS2   10                   // 10,9

// ---------------- scratch (no allocations allowed) ----------------
__device__ float g_p1[M1 * ATT];
__device__ float g_p2[M2 * ATT];
__device__ float g_p1part[(size_t)KSPLIT * M1 * ATT];
__device__ float g_p2part[(size_t)KSPLIT * M2 * ATT];
__device__ float g_v[ATT];
__device__ float g_cst;
__device__ __half g_a1[(size_t)M1 * K1CAT];
__device__ __half g_b1[(size_t)ATT * K1CAT];
__device__ __half g_a2[(size_t)M2 * K2CAT];
__device__ __half g_b2[(size_t)ATT * K2CAT];

// ---------------------------------------------------------------------------
// Split fp32 -> (hi, lo) fp16, K-concatenated: A:[hi|lo]  B:[hi|hi]
// Acat.Bcat = Ah.Bh + Al.Bh = A.Bh  (error = A.Bl ~ 2^-12 rel)
// ---------------------------------------------------------------------------
__global__ void __launch_bounds__(256) split_cat_kernel(
    const float* __restrict__ src, __half* __restrict__ dst,
    int total4, int Kq, int K, int Kcat, int bmode)
{
    int i = blockIdx.x * 256 + threadIdx.x;
    if (i >= total4) return;
    int r = i / Kq;
    int k = (i - r * Kq) * 4;

    float4 x = *reinterpret_cast<const float4*>(src + (size_t)r * K + k);
    float xs[4] = {x.x, x.y, x.z, x.w};
    unsigned short hs[4], ls[4];
#pragma unroll
    for (int j = 0; j < 4; j++) {
        __half h = __float2half_rn(xs[j]);
        __half l = __float2half_rn(xs[j] - __half2float(h));
        hs[j] = __half_as_ushort(h);
        ls[j] = __half_as_ushort(l);
    }
    uint2 H, L;
    H.x = (unsigned)hs[0] | ((unsigned)hs[1] << 16);
    H.y = (unsigned)hs[2] | ((unsigned)hs[3] << 16);
    L.x = (unsigned)ls[0] | ((unsigned)ls[1] << 16);
    L.y = (unsigned)ls[2] | ((unsigned)ls[3] << 16);

    size_t base = (size_t)r * Kcat + k;
    if (bmode == 0) {
        *reinterpret_cast<uint2*>(dst + base)     = H;
        *reinterpret_cast<uint2*>(dst + base + K) = L;
    } else {
        *reinterpret_cast<uint2*>(dst + base)     = H;
        *reinterpret_cast<uint2*>(dst + base + K) = H;
    }
}

// ---------------------------------------------------------------------------
// fp16 MMA GEMM NT, 5-stage cp.async pipeline, split-K partial outputs.
// Block 128x128, 256 thr (8 warps 2x4), warp 64x32, K-chunk 32.
// __launch_bounds__(256,2): force <=128 regs so 2 CTAs/SM co-reside.
// ---------------------------------------------------------------------------
#define STAGES 5
#define SROW 40                       // fp16 per smem row (80B)
#define STG_B (128 * SROW * 2)        // 10240 B per operand-stage
#define DSMEM (2 * STAGES * STG_B)    // 102400 B

__global__ void __launch_bounds__(256, 2) mma_gemm_nt_ms(
    const __half* __restrict__ A, const __half* __restrict__ Bm,
    float* __restrict__ Cpart, int M, int N, int Kld,
    int total_chunks, int chunks_per_split)
{
    extern __shared__ __align__(16) char smem_raw[];
    const uint32_t sA0 = (uint32_t)__cvta_generic_to_shared(smem_raw);
    const uint32_t sB0 = sA0 + STAGES * STG_B;

    const int t    = threadIdx.x;
    const int lane = t & 31;
    const int warp = t >> 5;
    const int wm   = (warp >> 2) * 64;
    const int wn   = (warp & 3) * 32;
    const int m0   = blockIdx.y * 128;
    const int n0   = blockIdx.x * 128;
    const int ks   = blockIdx.z;
    const int kbeg = ks * chunks_per_split;
    int nk = total_chunks - kbeg;
    if (nk > chunks_per_split) nk = chunks_per_split;
    float* __restrict__ C = Cpart + (size_t)ks * M * N;

    float c[4][4][4];
#pragma unroll
    for (int i = 0; i < 4; i++)
#pragma unroll
        for (int j = 0; j < 4; j++)
#pragma unroll
            for (int r = 0; r < 4; r++) c[i][j][r] = 0.0f;

    const int lrow0 = t >> 2;
    const int lseg  = (t & 3) * 8;

#define LOADC(kc, st) do {                                                    \
    _Pragma("unroll")                                                         \
    for (int it = 0; it < 2; it++) {                                          \
        int row = lrow0 + it * 64;                                            \
        int ga  = m0 + row;                                                   \
        const __half* srcA = A + (size_t)ga * Kld + (kc) * 32 + lseg;         \
        uint32_t dstA = sA0 + (st) * STG_B + row * (SROW * 2) + lseg * 2;     \
        int bytesA = (ga < M) ? 16 : 0;                                       \
        asm volatile("cp.async.cg.shared.global [%0], [%1], 16, %2;\n"        \
                     :: "r"(dstA), "l"(srcA), "r"(bytesA));                   \
        const __half* srcB = Bm + (size_t)(n0 + row) * Kld + (kc) * 32 + lseg; \
        uint32_t dstB = sB0 + (st) * STG_B + row * (SROW * 2) + lseg * 2;     \
        asm volatile("cp.async.cg.shared.global [%0], [%1], 16;\n"            \
                     :: "r"(dstB), "l"(srcB));                                \
    }                                                                          \
} while (0)

#define COMPUTEC(st) do {                                                     \
    _Pragma("unroll")                                                         \
    for (int ksub = 0; ksub < 2; ksub++) {                                    \
        int koff = ksub * 16;                                                 \
        uint32_t a[4][4];                                                     \
        _Pragma("unroll")                                                     \
        for (int i = 0; i < 4; i++) {                                         \
            uint32_t addr = sA0 + (st) * STG_B                                \
                + (wm + i * 16 + (lane & 15)) * (SROW * 2)                    \
                + ((lane >> 4) * 8 + koff) * 2;                               \
            asm volatile("ldmatrix.sync.aligned.m8n8.x4.shared.b16 "          \
                         "{%0,%1,%2,%3}, [%4];\n"                             \
                         : "=r"(a[i][0]), "=r"(a[i][1]),                      \
                           "=r"(a[i][2]), "=r"(a[i][3]) : "r"(addr));         \
        }                                                                     \
        uint32_t b[4][2];                                                     \
        _Pragma("unroll")                                                     \
        for (int j2 = 0; j2 < 2; j2++) {                                      \
            uint32_t addr = sB0 + (st) * STG_B                                \
                + (wn + j2 * 16 + (lane & 15)) * (SROW * 2)                   \
                + ((lane >> 4) * 8 + koff) * 2;                               \
            uint32_t r0, r1, r2, r3;                                          \
            asm volatile("ldmatrix.sync.aligned.m8n8.x4.shared.b16 "          \
                         "{%0,%1,%2,%3}, [%4];\n"                             \
                         : "=r"(r0), "=r"(r1), "=r"(r2), "=r"(r3)             \
                         : "r"(addr));                                        \
            b[2 * j2][0] = r0; b[2 * j2 + 1][0] = r1;                         \
            b[2 * j2][1] = r2; b[2 * j2 + 1][1] = r3;                         \
        }                                                                     \
        _Pragma("unroll")                                                     \
        for (int i = 0; i < 4; i++)                                           \
            _Pragma("unroll")                                                 \
            for (int j = 0; j < 4; j++)                                       \
                asm volatile(                                                 \
                  "mma.sync.aligned.m16n8k16.row.col.f32.f16.f16.f32 "        \
                  "{%0,%1,%2,%3}, {%4,%5,%6,%7}, {%8,%9}, {%0,%1,%2,%3};\n"   \
                  : "+f"(c[i][j][0]), "+f"(c[i][j][1]),                       \
                    "+f"(c[i][j][2]), "+f"(c[i][j][3])                        \
                  : "r"(a[i][0]), "r"(a[i][1]), "r"(a[i][2]), "r"(a[i][3]),   \
                    "r"(b[j][0]), "r"(b[j][1]));                              \
    }                                                                          \
} while (0)

    // prologue: fill STAGES-1 = 4 stages
#pragma unroll
    for (int s = 0; s < STAGES - 1; s++) {
        if (s < nk) LOADC(kbeg + s, s);
        asm volatile("cp.async.commit_group;\n");
    }

    int stc = 0;             // stage holding chunk i
    int stl = STAGES - 1;    // stage receiving chunk i + STAGES-1
    for (int i = 0; i < nk; i++) {
        asm volatile("cp.async.wait_group %0;\n" :: "n"(STAGES - 2));
        __syncthreads();
        int j = i + STAGES - 1;
        if (j < nk) LOADC(kbeg + j, stl);
        asm volatile("cp.async.commit_group;\n");
        COMPUTEC(stc);
        stc = (stc + 1 == STAGES) ? 0 : stc + 1;
        stl = (stl + 1 == STAGES) ? 0 : stl + 1;
    }

    // epilogue: raw partial (summed in reduce)
#pragma unroll
    for (int i = 0; i < 4; i++) {
        int row0 = m0 + wm + i * 16 + (lane >> 2);
#pragma unroll
        for (int j = 0; j < 4; j++) {
            int col = n0 + wn + j * 8 + (lane & 3) * 2;
            if (row0 < M) {
                float2 o = make_float2(c[i][j][0], c[i][j][1]);
                *reinterpret_cast<float2*>(&C[(size_t)row0 * N + col]) = o;
            }
            if (row0 + 8 < M) {
                float2 o = make_float2(c[i][j][2], c[i][j][3]);
                *reinterpret_cast<float2*>(&C[(size_t)(row0 + 8) * N + col]) = o;
            }
        }
    }
}

// ---------------------------------------------------------------------------
// Fused reduce of 2 partials: y==0 -> p1, y==1 -> p2
// ---------------------------------------------------------------------------
__global__ void __launch_bounds__(256) reduce2_both_kernel(
    const float* __restrict__ partA, float* __restrict__ dstA, int n4a,
    const float* __restrict__ partB, float* __restrict__ dstB, int n4b)
{
    int i = blockIdx.x * 256 + threadIdx.x;
    const float* part;
    float* dst;
    int n4;
    if (blockIdx.y == 0) { part = partA; dst = dstA; n4 = n4a; }
    else                 { part = partB; dst = dstB; n4 = n4b; }
    if (i >= n4) return;
    const float4* p = reinterpret_cast<const float4*>(part);
    float4 a = p[i];
    float4 b = p[i + (size_t)n4];
    float4 o;
    o.x = a.x + b.x;
    o.y = a.y + b.y;
    o.z = a.z + b.z;
    o.w = a.w + b.w;
    reinterpret_cast<float4*>(dst)[i] = o;
}

// ---------------------------------------------------------------------------
// blocks 0..7: v[a] = sum_c wt[c]*Wh[c][a] ; block 8: cst = dot(wt,bh)+bt
// ---------------------------------------------------------------------------
__global__ void __launch_bounds__(128) v_and_cst_kernel(
    const float* __restrict__ Wh, const float* __restrict__ wt,
    const float* __restrict__ bh, const float* __restrict__ bt)
{
    if (blockIdx.x < 8) {
        int a = blockIdx.x * 128 + threadIdx.x;
        float acc = 0.0f;
#pragma unroll 8
        for (int c = 0; c < ATT; c++)
            acc = fmaf(wt[c], Wh[(size_t)c * ATT + a], acc);
        g_v[a] = acc;
    } else {
        __shared__ float red[128];
        float acc = 0.0f;
        for (int i = threadIdx.x; i < ATT; i += 128)
            acc = fmaf(wt[i], bh[i], acc);
        red[threadIdx.x] = acc;
        __syncthreads();
        for (int s = 64; s > 0; s >>= 1) {
            if (threadIdx.x < s) red[threadIdx.x] += red[threadIdx.x + s];
            __syncthreads();
        }
        if (threadIdx.x == 0) g_cst = red[0] + bt[0];
    }
}

// ---------------------------------------------------------------------------
// alpha[b,l,p] = sum_a tanh(p1*p2)*v[a] + cst ;  tanh via MUFU.TANH (1 MUFU)
// ---------------------------------------------------------------------------
__global__ void __launch_bounds__(256) bilinear_tanh_kernel(
    float* __restrict__ out)
{
    __shared__ float p1s[128][17];
    __shared__ float p2s[128][17];
    __shared__ float vs[128];

    const int b  = blockIdx.z;
    const int l0 = blockIdx.y * 16;
    const int p0 = blockIdx.x * 16;
    const int t  = threadIdx.x;
    const int tx = t & 15;
    const int ty = t >> 4;

    const float* __restrict__ p1b = g_p1 + ((size_t)b * P_ + p0) * ATT;
    const float* __restrict__ p2b = g_p2 + ((size_t)b * L_ + l0) * ATT;

    float acc = 0.0f;

    for (int a0 = 0; a0 < ATT; a0 += 128) {
        __syncthreads();
        for (int i = t; i < 16 * 128; i += 256) {
            int r = i >> 7;
            int a = i & 127;
            float v1 = 0.0f;
            if (p0 + r < P_) v1 = p1b[(size_t)r * ATT + a0 + a];
            p1s[a][r] = v1;
            p2s[a][r] = p2b[(size_t)r * ATT + a0 + a];
        }
        if (t < 128) vs[t] = g_v[a0 + t];
        __syncthreads();

#pragma unroll 8
        for (int j = 0; j < 128; j++) {
            float arg = p1s[j][tx] * p2s[j][ty];
            float th;
            asm("tanh.approx.f32 %0, %1;" : "=f"(th) : "f"(arg));
            acc = fmaf(th, vs[j], acc);
        }
    }

    int p = p0 + tx;
    int l = l0 + ty;
    if (p < P_)
        out[((size_t)b * L_ + l) * P_ + p] = acc + g_cst;
}

// ---------------------------------------------------------------------------
extern "C" void kernel_launch(void* const* d_in, const int* in_sizes, int n_in,
                              void* d_out, int out_size)
{
    const float* x1 = (const float*)d_in[0];
    const float* x2 = (const float*)d_in[1];
    const float* W1 = (const float*)d_in[2];
    const float* W2 = (const float*)d_in[3];
    const float* Wh = (const float*)d_in[4];
    const float* bh = (const float*)d_in[5];
    const float* wt = (const float*)d_in[6];
    const float* bt = (const float*)d_in[7];
    float* out = (float*)d_out;

    void *p1_ptr, *p2_ptr, *p1p_ptr, *p2p_ptr, *a1_ptr, *b1_ptr, *a2_ptr, *b2_ptr;
    cudaGetSymbolAddress(&p1_ptr, g_p1);
    cudaGetSymbolAddress(&p2_ptr, g_p2);
    cudaGetSymbolAddress(&p1p_ptr, g_p1part);
    cudaGetSymbolAddress(&p2p_ptr, g_p2part);
    cudaGetSymbolAddress(&a1_ptr, g_a1);
    cudaGetSymbolAddress(&b1_ptr, g_b1);
    cudaGetSymbolAddress(&a2_ptr, g_a2);
    cudaGetSymbolAddress(&b2_ptr, g_b2);

    cudaFuncSetAttribute(mma_gemm_nt_ms,
                         cudaFuncAttributeMaxDynamicSharedMemorySize, DSMEM);

    // launches 0,1: zero gemm2 operand buffers (covers K-pad 600..608)
    cudaMemsetAsync(a2_ptr, 0, (size_t)M2 * K2CAT * sizeof(__half));
    cudaMemsetAsync(b2_ptr, 0, (size_t)ATT * K2CAT * sizeof(__half));

    // launches 2,3,4: splits needed before GEMM1 (x1, W1, x2)
    {
        int t4 = M1 * (D1 / 4);
        split_cat_kernel<<<(t4 + 255) / 256, 256>>>(x1, (__half*)a1_ptr,
                                                    t4, D1 / 4, D1, K1CAT, 0);
    }
    {
        int t4 = ATT * (D1 / 4);
        split_cat_kernel<<<(t4 + 255) / 256, 256>>>(W1, (__half*)b1_ptr,
                                                    t4, D1 / 4, D1, K1CAT, 1);
    }
    {
        int t4 = M2 * (D2 / 4);
        split_cat_kernel<<<(t4 + 255) / 256, 256>>>(x2, (__half*)a2_ptr,
                                                    t4, D2 / 4, D2, K2CAT, 0);
    }

    // launch 5 (ncu-profiled slot): GEMM1 partials, 208 CTAs = single wave
    {
        dim3 grid(ATT / 128, (M1 + 127) / 128, KSPLIT);
        mma_gemm_nt_ms<<<grid, 256, DSMEM>>>(
            (const __half*)a1_ptr, (const __half*)b1_ptr,
            (float*)p1p_ptr, M1, ATT, K1CAT, NK1, CPS1);
    }

    // launch 6: W2 split ; launch 7: GEMM2
    {
        int t4 = ATT * (D2 / 4);
        split_cat_kernel<<<(t4 + 255) / 256, 256>>>(W2, (__half*)b2_ptr,
                                                    t4, D2 / 4, D2, K2CAT, 1);
    }
    {
        dim3 grid(ATT / 128, (M2 + 127) / 128, KSPLIT);
        mma_gemm_nt_ms<<<grid, 256, DSMEM>>>(
            (const __half*)a2_ptr, (const __half*)b2_ptr,
            (float*)p2p_ptr, M2, ATT, K2CAT, NK2, CPS2);
    }

    // launch 8: fused reduce of both partial sets (2 splits each)
    {
        int n4a = M1 * ATT / 4;
        int n4b = M2 * ATT / 4;
        dim3 grid((n4a + 255) / 256, 2);
        reduce2_both_kernel<<<grid, 256>>>((const float*)p1p_ptr, (float*)p1_ptr,
                                           n4a,
                                           (const float*)p2p_ptr, (float*)p2_ptr,
                                           n4b);
    }

    // launch 9: v + cst fused
    v_and_cst_kernel<<<9, 128>>>(Wh, wt, bh, bt);

    // launch 10: main fused tanh-bilinear reduction
    {
        dim3 grid((P_ + 15) / 16, L_ / 16, B_);
        bilinear_tanh_kernel<<<grid, 256>>>(out);
    }
}